// round 13
// baseline (speedup 1.0000x reference)
#include <cuda_runtime.h>
#include <cuda_fp16.h>
#include <math.h>
#include <stdint.h>

// ---------------- problem constants ----------------
#define NTOK   4096              // B*N = 2*2048
#define DIMC   1024
#define NHEADS 16
#define DHEAD  64
#define MLPHID 716
#define FW     3788              // 3*DIM + MLP_HID (true width)
#define FWP    3840              // padded to 30*128
#define HIDPAD 768               // Wmo rows padded; K2 of apply
#define NSEQ   2048
#define LN_EPS 1e-6f
#define NSLICE 16
#define QSCALE 0.1803368801111204f   // 0.125 * log2(e): softmax in 2^s domain

// ---------------- scratch (static device globals) ------
__device__ __half g_norm [NTOK * DIMC];
__device__ __half g_fused[NTOK * FWP];
__device__ __half g_vt   [2 * NHEADS * DHEAD * NSEQ];   // V transposed [b][h][d][n]
__device__ __half g_attn [NTOK * DIMC];
__device__ __half g_w1t  [FWP  * DIMC];
__device__ __half g_w2t  [DIMC * 2 * DIMC];
__device__ __half g_waor [DIMC * DIMC];
__device__ __half g_wmor [HIDPAD * DIMC];
__device__ __half g_wfa  [DIMC * DIMC];
__device__ __half g_wfm  [DIMC * HIDPAD];
__device__ float  g_beff [DIMC];
__device__ float  g_beffp[NSLICE * DIMC];

// ================= helpers =================
__device__ __forceinline__ uint32_t smem_u32(const void* p) {
    uint32_t a;
    asm("{ .reg .u64 t; cvta.to.shared.u64 t, %1; cvt.u32.u64 %0, t; }" : "=r"(a) : "l"(p));
    return a;
}
__device__ __forceinline__ void mma_f16(float& d0, float& d1, float& d2, float& d3,
                                        uint32_t a0, uint32_t a1, uint32_t a2, uint32_t a3,
                                        uint32_t b0, uint32_t b1)
{
    asm volatile(
        "mma.sync.aligned.m16n8k16.row.col.f32.f16.f16.f32 "
        "{%0,%1,%2,%3}, {%4,%5,%6,%7}, {%8,%9}, {%0,%1,%2,%3};"
        : "+f"(d0), "+f"(d1), "+f"(d2), "+f"(d3)
        : "r"(a0), "r"(a1), "r"(a2), "r"(a3), "r"(b0), "r"(b1));
}
__device__ __forceinline__ void ldsm4(uint32_t& r0, uint32_t& r1, uint32_t& r2, uint32_t& r3,
                                      uint32_t addr)
{
    asm volatile("ldmatrix.sync.aligned.m8n8.x4.shared.b16 {%0,%1,%2,%3}, [%4];"
                 : "=r"(r0), "=r"(r1), "=r"(r2), "=r"(r3) : "r"(addr));
}
__device__ __forceinline__ void stsm4(uint32_t addr, uint32_t r0, uint32_t r1,
                                      uint32_t r2, uint32_t r3)
{
    asm volatile("stmatrix.sync.aligned.m8n8.x4.shared.b16 [%0], {%1,%2,%3,%4};"
                 :: "r"(addr), "r"(r0), "r"(r1), "r"(r2), "r"(r3) : "memory");
}
__device__ __forceinline__ float gelu1(float x) {
    float u = 0.7978845608028654f * (x + 0.044715f * x * x * x);
    return 0.5f * x * (1.f + tanhf(u));
}
__device__ __forceinline__ uint32_t h2pack(float a, float b) {
    __half2 h = __floats2half2_rn(a, b);
    return *reinterpret_cast<uint32_t*>(&h);
}
__device__ __forceinline__ uint32_t h2exp2(uint32_t v) {
    uint32_t r; asm("ex2.approx.f16x2 %0, %1;" : "=r"(r) : "r"(v)); return r;
}
__device__ __forceinline__ uint32_t h2minc(uint32_t v, uint32_t c) {
    __half2 a = *reinterpret_cast<__half2*>(&v);
    __half2 b = *reinterpret_cast<__half2*>(&c);
    __half2 m = __hmin2(a, b);
    return *reinterpret_cast<uint32_t*>(&m);
}
#define CP_CA(dst, src) asm volatile("cp.async.ca.shared.global [%0], [%1], 16;" :: "r"(dst), "l"(src) : "memory")
#define CP_CG(dst, src) asm volatile("cp.async.cg.shared.global [%0], [%1], 16;" :: "r"(dst), "l"(src) : "memory")
#define CP_COMMIT()     asm volatile("cp.async.commit_group;" ::: "memory")
#define CP_WAIT(n)      asm volatile("cp.async.wait_group %0;" :: "n"(n) : "memory")

// ============================================================
// prep_w1: W1 [1024 x 3788] -> w1t [3840][1024] (half), 3840 blocks
// ============================================================
__global__ void prep_w1_kernel(const float* __restrict__ W1)
{
    __shared__ float t[32][33];
    int bid = blockIdx.x, tid = threadIdx.x;
    int tx = tid & 31, ty = tid >> 5;
    int bx = bid % (FWP / 32), by = bid / (FWP / 32);
    int n0 = bx * 32, k0 = by * 32;
    #pragma unroll
    for (int i = 0; i < 32; i += 8) {
        int n = n0 + tx;
        t[ty + i][tx] = (n < FW) ? W1[(size_t)(k0 + ty + i) * FW + n] : 0.f;
    }
    __syncthreads();
    #pragma unroll
    for (int i = 0; i < 32; i += 8)
        g_w1t[(size_t)(n0 + ty + i) * DIMC + k0 + tx] = __float2half(t[tx][ty + i]);
}

// ============================================================
// prep_rest: W2^T, Wao copy, Wmo copy(pad), beff partials — 9280 blocks
// ============================================================
__global__ void prep_rest_kernel(const float* __restrict__ W2,
                                 const float* __restrict__ Wao,
                                 const float* __restrict__ Wmo,
                                 const float* __restrict__ bao,
                                 const float* __restrict__ bmo,
                                 const float* __restrict__ b2)
{
    __shared__ float t[32][33];
    int bid = blockIdx.x, tid = threadIdx.x;
    int tx = tid & 31, ty = tid >> 5;

    if (bid < 2048) {
        int bx = bid % 32, by = bid / 32;
        int n0 = bx * 32, k0 = by * 32;
        #pragma unroll
        for (int i = 0; i < 32; i += 8)
            t[ty + i][tx] = W2[(size_t)(k0 + ty + i) * DIMC + n0 + tx];
        __syncthreads();
        #pragma unroll
        for (int i = 0; i < 32; i += 8)
            g_w2t[(size_t)(n0 + ty + i) * 2 * DIMC + k0 + tx] = __float2half(t[tx][ty + i]);
    } else if (bid < 6144) {
        int idx = (bid - 2048) * 256 + tid;
        g_waor[idx] = __float2half(Wao[idx]);
    } else if (bid < 9216) {
        int idx = (bid - 6144) * 256 + tid;
        int r = idx >> 10, c = idx & 1023;
        g_wmor[idx] = (r < MLPHID) ? __float2half(Wmo[(size_t)r * DIMC + c])
                                   : __float2half(0.f);
    } else {
        int b = bid - 9216;
        int n = (b & 3) * 256 + tid;
        int s = b >> 2;
        float acc = (s == 0) ? b2[n] : 0.f;
        int k0 = s * (2048 / NSLICE), k1 = k0 + (2048 / NSLICE);
        for (int k = k0; k < k1; k++) {
            float c = (k < 1024) ? bao[k] : bmo[k - 1024];
            acc += c * W2[(size_t)k * DIMC + n];
        }
        g_beffp[s * DIMC + n] = acc;
    }
}

// ============================================================
// merged fold launch: BOTH weight folds + beff reduce, one wave.
// ============================================================
#define SSTRW 36
#define ABUFW (128 * SSTRW)
#define STAGEW (2 * ABUFW)
#define GEMM_SMEM (3 * STAGEW * 4)   // 110592 B

__global__ void __launch_bounds__(256, 2)
fold_kernel()
{
    extern __shared__ uint32_t smw[];
    int bid = blockIdx.x, tid = threadIdx.x;

    if (bid >= 112) {
        int n = (bid - 112) * 256 + tid;
        float s = 0.f;
        #pragma unroll
        for (int i = 0; i < NSLICE; i++) s += g_beffp[i * DIMC + n];
        g_beff[n] = s;
        return;
    }

    const __half* A; const __half* Bt; __half* C;
    int lda, ldb, ldc, bm, bn;
    if (bid < 64) {
        A = g_w2t;  lda = 2 * DIMC; Bt = g_waor; ldb = DIMC;
        C = g_wfa;  ldc = DIMC;
        bn = (bid & 7) * 128; bm = (bid >> 3) * 128;
    } else {
        int b = bid - 64;
        A = g_w2t + DIMC; lda = 2 * DIMC; Bt = g_wmor; ldb = DIMC;
        C = g_wfm; ldc = HIDPAD;
        bn = (b % 6) * 128; bm = (b / 6) * 128;
    }

    uint32_t sbase = smem_u32(smw);
    int wid = tid >> 5, lane = tid & 31;
    int quad = lane >> 2, tig = lane & 3;
    int wm = (wid & 1) * 64, wn = (wid >> 1) * 32;
    int lr = tid >> 3, lcw = (tid & 7) * 4;
    int lane15 = lane & 15;

    float acc[4][4][4];
    #pragma unroll
    for (int i = 0; i < 4; i++)
        #pragma unroll
        for (int j = 0; j < 4; j++)
            #pragma unroll
            for (int r = 0; r < 4; r++) acc[i][j][r] = 0.f;

    uint32_t aoff[4];
    #pragma unroll
    for (int mt = 0; mt < 4; mt++)
        aoff[mt] = (uint32_t)((wm + mt * 16 + lane15) * SSTRW) * 4 + (lane >> 4) * 16;
    uint32_t boff0 = (uint32_t)((wn + ((lane >> 4) << 3) + (lane & 7)) * SSTRW) * 4
                   + ((lane >> 3) & 1) * 16;
    uint32_t boff1 = boff0 + 16 * SSTRW * 4;

    const int nk = DIMC >> 6;     // 16

    auto prefetch = [&](int it, int st) {
        int k0 = it << 6;
        uint32_t dA = sbase + (uint32_t)st * STAGEW * 4;
        uint32_t dB = dA + ABUFW * 4;
        #pragma unroll
        for (int i = 0; i < 4; i++) {
            int r = i * 32 + lr;
            CP_CG(dA + (uint32_t)(r * SSTRW + lcw) * 4, A + (size_t)(bm + r) * lda + k0 + lcw * 2);
            CP_CG(dB + (uint32_t)(r * SSTRW + lcw) * 4, Bt + (size_t)(bn + r) * ldb + k0 + lcw * 2);
        }
        CP_COMMIT();
    };

    prefetch(0, 0);
    prefetch(1, 1);

    for (int it = 0; it < nk; it++) {
        if (it == nk - 1) { CP_WAIT(0); } else { CP_WAIT(1); }
        __syncthreads();

        uint32_t stA = sbase + (uint32_t)(it % 3) * STAGEW * 4;
        uint32_t stB = stA + ABUFW * 4;
        #pragma unroll
        for (int kk = 0; kk < 4; kk++) {
            uint32_t af[4][4], bf[4][2];
            #pragma unroll
            for (int mt = 0; mt < 4; mt++)
                ldsm4(af[mt][0], af[mt][1], af[mt][2], af[mt][3],
                      stA + aoff[mt] + kk * 32);
            ldsm4(bf[0][0], bf[0][1], bf[1][0], bf[1][1], stB + boff0 + kk * 32);
            ldsm4(bf[2][0], bf[2][1], bf[3][0], bf[3][1], stB + boff1 + kk * 32);
            #pragma unroll
            for (int mt = 0; mt < 4; mt++)
                #pragma unroll
                for (int nt = 0; nt < 4; nt++)
                    mma_f16(acc[mt][nt][0], acc[mt][nt][1],
                            acc[mt][nt][2], acc[mt][nt][3],
                            af[mt][0], af[mt][1], af[mt][2], af[mt][3],
                            bf[nt][0], bf[nt][1]);
        }
        if (it + 2 < nk) prefetch(it + 2, (it + 2) % 3);
    }

    #pragma unroll
    for (int mt = 0; mt < 4; mt++) {
        int r0 = bm + wm + mt * 16 + quad;
        #pragma unroll
        for (int nt = 0; nt < 4; nt++) {
            int c = bn + wn + nt * 8 + tig * 2;
            *reinterpret_cast<uint32_t*>(C + (size_t)r0 * ldc + c) =
                h2pack(acc[mt][nt][0], acc[mt][nt][1]);
            *reinterpret_cast<uint32_t*>(C + (size_t)(r0 + 8) * ldc + c) =
                h2pack(acc[mt][nt][2], acc[mt][nt][3]);
        }
    }
}

// ============================================================
// LayerNorm over DIM=1024, half output
// ============================================================
__global__ void ln_kernel(const float* __restrict__ x,
                          const float* __restrict__ g,
                          const float* __restrict__ b,
                          __half* __restrict__ out)
{
    int row = blockIdx.x;
    int tid = threadIdx.x;
    const float4 v = reinterpret_cast<const float4*>(x + (size_t)row * DIMC)[tid];

    float s  = v.x + v.y + v.z + v.w;
    float sq = v.x*v.x + v.y*v.y + v.z*v.z + v.w*v.w;
    #pragma unroll
    for (int o = 16; o > 0; o >>= 1) {
        s  += __shfl_xor_sync(0xffffffffu, s,  o);
        sq += __shfl_xor_sync(0xffffffffu, sq, o);
    }
    __shared__ float ws[8], wq[8];
    int warp = tid >> 5, lane = tid & 31;
    if (lane == 0) { ws[warp] = s; wq[warp] = sq; }
    __syncthreads();
    if (warp == 0) {
        float s2  = (lane < 8) ? ws[lane] : 0.f;
        float sq2 = (lane < 8) ? wq[lane] : 0.f;
        #pragma unroll
        for (int o = 4; o > 0; o >>= 1) {
            s2  += __shfl_xor_sync(0xffffffffu, s2,  o);
            sq2 += __shfl_xor_sync(0xffffffffu, sq2, o);
        }
        if (lane == 0) { ws[0] = s2; wq[0] = sq2; }
    }
    __syncthreads();
    float mean = ws[0] * (1.f / DIMC);
    float var  = wq[0] * (1.f / DIMC) - mean * mean;
    float rstd = rsqrtf(var + LN_EPS);

    float4 gg = reinterpret_cast<const float4*>(g)[tid];
    float4 bb = reinterpret_cast<const float4*>(b)[tid];
    uint2 o2;
    o2.x = h2pack((v.x - mean) * rstd * gg.x + bb.x,
                  (v.y - mean) * rstd * gg.y + bb.y);
    o2.y = h2pack((v.z - mean) * rstd * gg.z + bb.z,
                  (v.w - mean) * rstd * gg.w + bb.w);
    reinterpret_cast<uint2*>(out + (size_t)row * DIMC)[tid] = o2;
}

// ============================================================
// fp16 mma.sync GEMM, 3-stage cp.async pipeline, ldmatrix frags.
// mode 1: GEMM1-qkv — region 0 (qk): fused per-head LN (+log2 q scale)
//                     region 1: V->g_vt transposed
// mode 3: GEMM1-mlp slice: gelu epilogue, half out
// mode 2: C float + bias + resid (apply)    mode 0: plain half out
// mrow0: global row offset (token-half split of GEMM1)
// ============================================================
__global__ void __launch_bounds__(256, 2)
mma_gemm(const __half* __restrict__ A, int lda,
         const __half* __restrict__ Bt, int ldb, int K1,
         const __half* __restrict__ A2, int lda2,
         const __half* __restrict__ Bt2, int ldb2, int K2,
         __half* __restrict__ Ch, int ldch,
         float* __restrict__ Cf, int ldcf,
         const float* __restrict__ bias, int nbias,
         const float* __restrict__ resid, int ldr,
         const float* __restrict__ qg, const float* __restrict__ qb,
         const float* __restrict__ kg, const float* __restrict__ kb,
         int mrow0, int mode)
{
    extern __shared__ uint32_t smw[];
    uint32_t sbase = smem_u32(smw);
    int tid  = threadIdx.x;
    int wid  = tid >> 5, lane = tid & 31;
    int quad = lane >> 2, tig = lane & 3;
    int bm = blockIdx.y * 128 + mrow0, bn = blockIdx.x * 128;
    int wm = (wid & 1) * 64, wn = (wid >> 1) * 32;

    float acc[4][4][4];
    #pragma unroll
    for (int i = 0; i < 4; i++)
        #pragma unroll
        for (int j = 0; j < 4; j++)
            #pragma unroll
            for (int r = 0; r < 4; r++) acc[i][j][r] = 0.f;

    int lr = tid >> 3;
    int lcw = (tid & 7) * 4;

    int lane15 = lane & 15;
    uint32_t aoff[4];
    #pragma unroll
    for (int mt = 0; mt < 4; mt++)
        aoff[mt] = (uint32_t)((wm + mt * 16 + lane15) * SSTRW) * 4 + (lane >> 4) * 16;
    uint32_t boff0 = (uint32_t)((wn + ((lane >> 4) << 3) + (lane & 7)) * SSTRW) * 4
                   + ((lane >> 3) & 1) * 16;
    uint32_t boff1 = boff0 + 16 * SSTRW * 4;

    const int nk1 = K1 >> 6;
    const int nk  = nk1 + (K2 >> 6);

    auto prefetch = [&](int it, int st) {
        const __half* Ab; const __half* Bb; int la, lb, k0;
        if (it < nk1) { Ab = A;  Bb = Bt;  la = lda;  lb = ldb;  k0 = it << 6; }
        else          { Ab = A2; Bb = Bt2; la = lda2; lb = ldb2; k0 = (it - nk1) << 6; }
        uint32_t dA = sbase + (uint32_t)st * STAGEW * 4;
        uint32_t dB = dA + ABUFW * 4;
        #pragma unroll
        for (int i = 0; i < 4; i++) {
            int r = i * 32 + lr;
            CP_CG(dA + (uint32_t)(r * SSTRW + lcw) * 4, Ab + (size_t)(bm + r) * la + k0 + lcw * 2);
            CP_CG(dB + (uint32_t)(r * SSTRW + lcw) * 4, Bb + (size_t)(bn + r) * lb + k0 + lcw * 2);
        }
        CP_COMMIT();
    };

    prefetch(0, 0);
    if (nk > 1) prefetch(1, 1);

    for (int it = 0; it < nk; it++) {
        if (it == nk - 1) { CP_WAIT(0); } else { CP_WAIT(1); }
        __syncthreads();

        uint32_t stA = sbase + (uint32_t)(it % 3) * STAGEW * 4;
        uint32_t stB = stA + ABUFW * 4;

        #pragma unroll
        for (int kk = 0; kk < 4; kk++) {
            uint32_t af[4][4], bf[4][2];
            #pragma unroll
            for (int mt = 0; mt < 4; mt++)
                ldsm4(af[mt][0], af[mt][1], af[mt][2], af[mt][3],
                      stA + aoff[mt] + kk * 32);
            ldsm4(bf[0][0], bf[0][1], bf[1][0], bf[1][1], stB + boff0 + kk * 32);
            ldsm4(bf[2][0], bf[2][1], bf[3][0], bf[3][1], stB + boff1 + kk * 32);
            #pragma unroll
            for (int mt = 0; mt < 4; mt++)
                #pragma unroll
                for (int nt = 0; nt < 4; nt++)
                    mma_f16(acc[mt][nt][0], acc[mt][nt][1],
                            acc[mt][nt][2], acc[mt][nt][3],
                            af[mt][0], af[mt][1], af[mt][2], af[mt][3],
                            bf[nt][0], bf[nt][1]);
        }
        if (it + 2 < nk) prefetch(it + 2, (it + 2) % 3);
    }
    __syncthreads();   // protect smem reuse in region-0 epilogue

    int region = (mode != 1) ? -1 : ((bn < 2 * DIMC) ? 0 : 1);

    if (region == 0) {
        float* ssum = reinterpret_cast<float*>(smw);       // [128][4]
        float* ssq  = ssum + 128 * 4;                      // [128][4]
        int ch = wn >> 5;

        #pragma unroll
        for (int mt = 0; mt < 4; mt++) {
            float slo = 0.f, sqlo = 0.f, shi = 0.f, sqhi = 0.f;
            #pragma unroll
            for (int nt = 0; nt < 4; nt++) {
                int c = bn + wn + nt * 8 + tig * 2;
                float b0 = bias[c], b1v = bias[c + 1];
                acc[mt][nt][0] += b0; acc[mt][nt][1] += b1v;
                acc[mt][nt][2] += b0; acc[mt][nt][3] += b1v;
                slo  += acc[mt][nt][0] + acc[mt][nt][1];
                sqlo += acc[mt][nt][0] * acc[mt][nt][0] + acc[mt][nt][1] * acc[mt][nt][1];
                shi  += acc[mt][nt][2] + acc[mt][nt][3];
                sqhi += acc[mt][nt][2] * acc[mt][nt][2] + acc[mt][nt][3] * acc[mt][nt][3];
            }
            slo  += __shfl_xor_sync(0xffffffffu, slo, 1);
            slo  += __shfl_xor_sync(0xffffffffu, slo, 2);
            sqlo += __shfl_xor_sync(0xffffffffu, sqlo, 1);
            sqlo += __shfl_xor_sync(0xffffffffu, sqlo, 2);
            shi  += __shfl_xor_sync(0xffffffffu, shi, 1);
            shi  += __shfl_xor_sync(0xffffffffu, shi, 2);
            sqhi += __shfl_xor_sync(0xffffffffu, sqhi, 1);
            sqhi += __shfl_xor_sync(0xffffffffu, sqhi, 2);
            if (tig == 0) {
                int rl = wm + mt * 16 + quad;
                ssum[rl * 4 + ch] = slo;        ssq[rl * 4 + ch] = sqlo;
                ssum[(rl + 8) * 4 + ch] = shi;  ssq[(rl + 8) * 4 + ch] = sqhi;
            }
        }
        __syncthreads();

        int hb = (wn >> 6) << 1;
        bool isq = (bn < DIMC);
        const float* gv = isq ? qg : kg;
        const float* bv = isq ? qb : kb;
        float qsc = isq ? QSCALE : 1.f;

        #pragma unroll
        for (int mt = 0; mt < 4; mt++) {
            int rl = wm + mt * 16 + quad;
            float mlo = (ssum[rl * 4 + hb] + ssum[rl * 4 + hb + 1]) * (1.f / 64.f);
            float vlo = (ssq[rl * 4 + hb] + ssq[rl * 4 + hb + 1]) * (1.f / 64.f) - mlo * mlo;
            float rlo = rsqrtf(vlo + LN_EPS);
            float mhi = (ssum[(rl + 8) * 4 + hb] + ssum[(rl + 8) * 4 + hb + 1]) * (1.f / 64.f);
            float vhi = (ssq[(rl + 8) * 4 + hb] + ssq[(rl + 8) * 4 + hb + 1]) * (1.f / 64.f) - mhi * mhi;
            float rhi = rsqrtf(vhi + LN_EPS);
            int r0 = bm + rl;
            #pragma unroll
            for (int nt = 0; nt < 4; nt++) {
                int c = bn + wn + nt * 8 + tig * 2;
                int d = c & 63;
                float g0 = gv[d], g1 = gv[d + 1];
                float e0 = bv[d], e1 = bv[d + 1];
                float o0 = ((acc[mt][nt][0] - mlo) * rlo * g0 + e0) * qsc;
                float o1 = ((acc[mt][nt][1] - mlo) * rlo * g1 + e1) * qsc;
                float o2 = ((acc[mt][nt][2] - mhi) * rhi * g0 + e0) * qsc;
                float o3 = ((acc[mt][nt][3] - mhi) * rhi * g1 + e1) * qsc;
                *reinterpret_cast<uint32_t*>(Ch + (size_t)r0 * ldch + c) = h2pack(o0, o1);
                *reinterpret_cast<uint32_t*>(Ch + (size_t)(r0 + 8) * ldch + c) = h2pack(o2, o3);
            }
        }
        return;
    }

    #pragma unroll
    for (int mt = 0; mt < 4; mt++) {
        int r0 = bm + wm + mt * 16 + quad;
        #pragma unroll
        for (int nt = 0; nt < 4; nt++) {
            int c = bn + wn + nt * 8 + tig * 2;
            float2 v0 = make_float2(acc[mt][nt][0], acc[mt][nt][1]);
            float2 v1 = make_float2(acc[mt][nt][2], acc[mt][nt][3]);
            if (bias) {
                float bx = (c     < nbias) ? bias[c]     : 0.f;
                float by = (c + 1 < nbias) ? bias[c + 1] : 0.f;
                v0.x += bx; v0.y += by;
                v1.x += bx; v1.y += by;
            }
            if (mode == 2) {
                float2 ra = *reinterpret_cast<const float2*>(resid + (size_t)r0 * ldr + c);
                float2 rb = *reinterpret_cast<const float2*>(resid + (size_t)(r0 + 8) * ldr + c);
                v0.x += ra.x; v0.y += ra.y;
                v1.x += rb.x; v1.y += rb.y;
                *reinterpret_cast<float2*>(Cf + (size_t)r0 * ldcf + c) = v0;
                *reinterpret_cast<float2*>(Cf + (size_t)(r0 + 8) * ldcf + c) = v1;
            } else if (region == 1) {
                int d = c - 2 * DIMC;
                int hh = d >> 6, dd = d & 63;
                int bbk = r0 >> 11, nn = r0 & 2047;
                size_t base = ((size_t)(bbk * NHEADS + hh) * DHEAD);
                g_vt[(base + dd    ) * NSEQ + nn    ] = __float2half(v0.x);
                g_vt[(base + dd + 1) * NSEQ + nn    ] = __float2half(v0.y);
                g_vt[(base + dd    ) * NSEQ + nn + 8] = __float2half(v1.x);
                g_vt[(base + dd + 1) * NSEQ + nn + 8] = __float2half(v1.y);
            } else {
                if (mode == 3) {
                    v0.x = gelu1(v0.x); v0.y = gelu1(v0.y);
                    v1.x = gelu1(v1.x); v1.y = gelu1(v1.y);
                }
                *reinterpret_cast<uint32_t*>(Ch + (size_t)r0 * ldch + c) = h2pack(v0.x, v0.y);
                *reinterpret_cast<uint32_t*>(Ch + (size_t)(r0 + 8) * ldch + c) = h2pack(v1.x, v1.y);
            }
        }
    }
}

// ============================================================
// Flash attention: fp16 m16n8k16, no online max (LN-bounded scores),
// p = 2^s via ex2.approx.f16x2 (log2e folded into q), row-sum l via
// one extra MMA against an all-ones B fragment. bbase = batch offset.
// ============================================================
#define KSTRW 36
#define QWORDS (128 * KSTRW)
#define KVWORDS (64 * KSTRW)
#define ATTN_SMEM ((QWORDS + 4 * KVWORDS) * 4)   // 55296 B
#define ONESF  0x3C003C00u
#define CLAMP2 0x4BC04BC0u   // half2(15.5); score bound is ~13.3

__global__ void __launch_bounds__(256, 2)
fattn_kernel(const __half* __restrict__ fused, __half* __restrict__ aout, int bbase)
{
    extern __shared__ uint32_t smw[];
    uint32_t sbase = smem_u32(smw);

    int tid  = threadIdx.x;
    int wid  = tid >> 5, lane = tid & 31;
    int quad = lane >> 2, tig = lane & 3;
    int lane15 = lane & 15;
    int h  = blockIdx.y;
    int bb = blockIdx.z + bbase;
    int q0 = blockIdx.x * 128;
    int tq0 = bb * NSEQ + q0;
    int kvb = bb * NSEQ;
    const __half* vtb = g_vt + (size_t)(bb * NHEADS + h) * DHEAD * NSEQ;

    auto prefetch_kv = [&](int kt, int buf) {
        uint32_t dK = sbase + (uint32_t)(QWORDS + buf * 2 * KVWORDS) * 4;
        uint32_t dV = dK + KVWORDS * 4;
        #pragma unroll
        for (int i = 0; i < 2; i++) {
            int idx = i * 256 + tid;
            int r = idx >> 3, chh = (idx & 7) * 8;
            CP_CG(dK + (uint32_t)(r * KSTRW + chh / 2) * 4,
                  fused + (size_t)(kvb + kt + r) * FWP + DIMC + h * DHEAD + chh);
            CP_CG(dV + (uint32_t)(r * KSTRW + chh / 2) * 4,
                  vtb + (size_t)r * NSEQ + kt + chh);
        }
        CP_COMMIT();
    };

    #pragma unroll
    for (int i = 0; i < 4; i++) {
        int idx = i * 256 + tid;
        int r = idx >> 3, chh = (idx & 7) * 8;
        CP_CA(sbase + (uint32_t)(r * KSTRW + chh / 2) * 4,
              fused + (size_t)(tq0 + r) * FWP + h * DHEAD + chh);
    }
    prefetch_kv(0, 0);
    CP_WAIT(0);
    __syncthreads();

    uint32_t aPat = (uint32_t)(lane15 * KSTRW) * 4 + (lane >> 4) * 16;
    uint32_t bPat = (uint32_t)((((lane >> 4) << 3) + (lane & 7)) * KSTRW) * 4
                  + ((lane >> 3) & 1) * 16;
    uint32_t sPat = (uint32_t)(((((lane >> 3) & 1) << 3) + (lane & 7)) * KSTRW) * 4
                  + (lane >> 4) * 16;

    uint32_t qf[4][4];
    {
        uint32_t qbase = sbase + (uint32_t)(wid * 16 * KSTRW) * 4 + aPat;
        #pragma unroll
        for (int kc = 0; kc < 4; kc++)
            ldsm4(qf[kc][0], qf[kc][1], qf[kc][2], qf[kc][3], qbase + kc * 32);
    }
    uint32_t pBase = sbase + (uint32_t)(wid * 16 * KSTRW) * 4;

    float o[8][4];
    #pragma unroll
    for (int i = 0; i < 8; i++)
        #pragma unroll
        for (int j = 0; j < 4; j++) o[i][j] = 0.f;
    float ls[4] = {0.f, 0.f, 0.f, 0.f};

    for (int t = 0; t < NSEQ / 64; t++) {
        int b = t & 1;
        if (t + 1 < NSEQ / 64) prefetch_kv((t + 1) * 64, b ^ 1);

        uint32_t kBase = sbase + (uint32_t)(QWORDS + b * 2 * KVWORDS) * 4;
        uint32_t vBase = kBase + KVWORDS * 4;

        float sc[8][4];
        #pragma unroll
        for (int i = 0; i < 8; i++)
            #pragma unroll
            for (int j = 0; j < 4; j++) sc[i][j] = 0.f;

        #pragma unroll
        for (int kc = 0; kc < 4; kc++) {
            #pragma unroll
            for (int np = 0; np < 4; np++) {
                uint32_t b00, b01, b10, b11;
                ldsm4(b00, b01, b10, b11,
                      kBase + (uint32_t)(np * 16 * KSTRW) * 4 + bPat + kc * 32);
                mma_f16(sc[2*np][0], sc[2*np][1], sc[2*np][2], sc[2*np][3],
                        qf[kc][0], qf[kc][1], qf[kc][2], qf[kc][3], b00, b01);
                mma_f16(sc[2*np+1][0], sc[2*np+1][1], sc[2*np+1][2], sc[2*np+1][3],
                        qf[kc][0], qf[kc][1], qf[kc][2], qf[kc][3], b10, b11);
            }
        }

        uint32_t hl0[8], hl1[8];
        #pragma unroll
        for (int nf = 0; nf < 8; nf++) {
            hl0[nf] = h2exp2(h2minc(h2pack(sc[nf][0], sc[nf][1]), CLAMP2));
            hl1[nf] = h2exp2(h2minc(h2pack(sc[nf][2], sc[nf][3]), CLAMP2));
        }
        #pragma unroll
        for (int np = 0; np < 4; np++)
            stsm4(pBase + sPat + np * 32,
                  hl0[2*np], hl1[2*np], hl0[2*np+1], hl1[2*np+1]);
        __syncwarp();

        #pragma unroll
        for (int kc = 0; kc < 4; kc++) {
            uint32_t a0, a1, a2, a3;
            ldsm4(a0, a1, a2, a3, pBase + aPat + kc * 32);
            mma_f16(ls[0], ls[1], ls[2], ls[3], a0, a1, a2, a3, ONESF, ONESF);
            #pragma unroll
            for (int np = 0; np < 4; np++) {
                uint32_t b00, b01, b10, b11;
                ldsm4(b00, b01, b10, b11,
                      vBase + (uint32_t)(np * 16 * KSTRW) * 4 + bPat + kc * 32);
                mma_f16(o[2*np][0], o[2*np][1], o[2*np][2], o[2*np][3],
                        a0, a1, a2, a3, b00, b01);
                mma_f16(o[2*np+1][0], o[2*np+1][1], o[2*np+1][2], o[2*np+1][3],
                        a0, a1, a2, a3, b10, b11);
            }
        }
        __syncwarp();

        if (t + 1 < NSEQ / 64) { CP_WAIT(0); }
        __syncthreads();
    }

    float il0 = 1.f / ls[0], il1 = 1.f / ls[2];
    int r0 = tq0 + wid * 16 + quad;
    #pragma unroll
    for (int nf = 0; nf < 8; nf++) {
        int c = h * DHEAD + nf * 8 + tig * 2;
        *reinterpret_cast<uint32_t*>(aout + (size_t)r0 * DIMC + c) =
            h2pack(o[nf][0] * il0, o[nf][1] * il0);
        *reinterpret_cast<uint32_t*>(aout + (size_t)(r0 + 8) * DIMC + c) =
            h2pack(o[nf][2] * il1, o[nf][3] * il1);
    }
}

// ============================================================
// launch — 3-stream pipelined DAG (graph-capture compatible)
// ============================================================
extern "C" void kernel_launch(void* const* d_in, const int* in_sizes, int n_in,
                              void* d_out, int out_size)
{
    const float* x      = (const float*)d_in[0];
    const float* norm_g = (const float*)d_in[1];
    const float* norm_b = (const float*)d_in[2];
    const float* W1     = (const float*)d_in[3];
    const float* b1     = (const float*)d_in[4];
    const float* qn_g   = (const float*)d_in[5];
    const float* qn_b   = (const float*)d_in[6];
    const float* kn_g   = (const float*)d_in[7];
    const float* kn_b   = (const float*)d_in[8];
    const float* Wao    = (const float*)d_in[9];
    const float* bao    = (const float*)d_in[10];
    const float* Wmo    = (const float*)d_in[11];
    const float* bmo    = (const float*)d_in[12];
    const float* W2     = (const float*)d_in[13];
    const float* b2     = (const float*)d_in[14];
    float*       out    = (float*)d_out;

    __half *norm, *fused, *attn, *w1t, *wfa, *wfm;
    float *beff;
    cudaGetSymbolAddress((void**)&norm,  g_norm);
    cudaGetSymbolAddress((void**)&fused, g_fused);
    cudaGetSymbolAddress((void**)&attn,  g_attn);
    cudaGetSymbolAddress((void**)&w1t,   g_w1t);
    cudaGetSymbolAddress((void**)&wfa,   g_wfa);
    cudaGetSymbolAddress((void**)&wfm,   g_wfm);
    cudaGetSymbolAddress((void**)&beff,  g_beff);

    static bool inited = false;
    static cudaStream_t s2, s3;
    static cudaEvent_t ev1, evw1, evln, evq0, evf0, evm;
    if (!inited) {
        cudaStreamCreateWithFlags(&s2, cudaStreamNonBlocking);
        cudaStreamCreateWithFlags(&s3, cudaStreamNonBlocking);
        cudaEventCreateWithFlags(&ev1, cudaEventDisableTiming);
        cudaEventCreateWithFlags(&evw1, cudaEventDisableTiming);
        cudaEventCreateWithFlags(&evln, cudaEventDisableTiming);
        cudaEventCreateWithFlags(&evq0, cudaEventDisableTiming);
        cudaEventCreateWithFlags(&evf0, cudaEventDisableTiming);
        cudaEventCreateWithFlags(&evm, cudaEventDisableTiming);
        cudaFuncSetAttribute(mma_gemm, cudaFuncAttributeMaxDynamicSharedMemorySize, GEMM_SMEM);
        cudaFuncSetAttribute(fold_kernel, cudaFuncAttributeMaxDynamicSharedMemorySize, GEMM_SMEM);
        cudaFuncSetAttribute(fattn_kernel, cudaFuncAttributeMaxDynamicSharedMemorySize, ATTN_SMEM);
        inited = true;
    }

    // ---- fork side chain s2: prep_w1 -> prep_rest -> fold -> mlp -> apply_m
    cudaEventRecord(ev1, 0);
    cudaStreamWaitEvent(s2, ev1, 0);
    prep_w1_kernel<<<3840, 256, 0, s2>>>(W1);
    cudaEventRecord(evw1, s2);
    prep_rest_kernel<<<9280, 256, 0, s2>>>(W2, Wao, Wmo, bao, bmo, b2);
    fold_kernel<<<116, 256, GEMM_SMEM, s2>>>();

    // ---- main: ln concurrent with prep_w1
    ln_kernel<<<NTOK, 256>>>(x, norm_g, norm_b, norm);
    cudaEventRecord(evln, 0);
    cudaStreamWaitEvent(0, evw1, 0);

    // s2: mlp slice (needs ln + w1t only; disjoint fused columns)
    cudaStreamWaitEvent(s2, evln, 0);
    mma_gemm<<<dim3(6, NTOK / 128), 256, GEMM_SMEM, s2>>>(
        norm, DIMC, w1t + (size_t)(3 * DIMC) * DIMC, DIMC, DIMC,
        nullptr, 0, nullptr, 0, 0,
        fused + 3 * DIMC, FWP, nullptr, 0, b1 + 3 * DIMC, FW - 3 * DIMC, nullptr, 0,
        nullptr, nullptr, nullptr, nullptr, 0, 3);
    // s2: apply_m: out = x + beff + gelu_hidden @ wfm^T   (under fattn)
    mma_gemm<<<dim3(DIMC / 128, NTOK / 128), 256, GEMM_SMEM, s2>>>(
        fused + 3 * DIMC, FWP, wfm, HIDPAD, HIDPAD,
        nullptr, 0, nullptr, 0, 0,
        nullptr, 0, out, DIMC, beff, DIMC, x, DIMC,
        nullptr, nullptr, nullptr, nullptr, 0, 2);
    cudaEventRecord(evm, s2);

    // ---- main: GEMM1-qkv token-half 0, then half 1
    mma_gemm<<<dim3(24, 16), 256, GEMM_SMEM>>>(
        norm, DIMC, w1t, DIMC, DIMC,
        nullptr, 0, nullptr, 0, 0,
        fused, FWP, nullptr, 0, b1, FW, nullptr, 0,
        qn_g, qn_b, kn_g, kn_b, 0, 1);
    cudaEventRecord(evq0, 0);
    mma_gemm<<<dim3(24, 16), 256, GEMM_SMEM>>>(
        norm, DIMC, w1t, DIMC, DIMC,
        nullptr, 0, nullptr, 0, 0,
        fused, FWP, nullptr, 0, b1, FW, nullptr, 0,
        qn_g, qn_b, kn_g, kn_b, 2048, 1);

    // s3: fattn batch 0 overlaps GEMM1 half 1
    cudaStreamWaitEvent(s3, evq0, 0);
    fattn_kernel<<<dim3(NSEQ / 128, NHEADS, 1), 256, ATTN_SMEM, s3>>>(fused, attn, 0);
    cudaEventRecord(evf0, s3);

    // main: fattn batch 1 (after GEMM1 half 1, in-stream)
    fattn_kernel<<<dim3(NSEQ / 128, NHEADS, 1), 256, ATTN_SMEM>>>(fused, attn, 1);

    // ---- join: apply_a: out += attn @ wfa^T
    cudaStreamWaitEvent(0, evf0, 0);
    cudaStreamWaitEvent(0, evm, 0);
    mma_gemm<<<dim3(DIMC / 128, NTOK / 128), 256, GEMM_SMEM>>>(
        attn, DIMC, wfa, DIMC, DIMC,
        nullptr, 0, nullptr, 0, 0,
        nullptr, 0, out, DIMC, nullptr, 0, out, DIMC,
        nullptr, nullptr, nullptr, nullptr, 0, 2);
}

// round 14
// speedup vs baseline: 1.4733x; 1.4733x over previous
#include <cuda_runtime.h>
#include <cuda_fp16.h>
#include <math.h>
#include <stdint.h>

// ---------------- problem constants ----------------
#define NTOK   4096              // B*N = 2*2048
#define DIMC   1024
#define NHEADS 16
#define DHEAD  64
#define MLPHID 716
#define FW     3788              // 3*DIM + MLP_HID (true width)
#define FWP    3840              // padded to 30*128
#define HIDPAD 768               // Wmo rows padded; K2 of apply
#define NSEQ   2048
#define LN_EPS 1e-6f
#define NSLICE 16
#define QSCALE 0.1803368801111204f   // 0.125 * log2(e): softmax in 2^s domain

// ---------------- scratch (static device globals) ------
__device__ __half g_norm [NTOK * DIMC];
__device__ __half g_fused[NTOK * FWP];
__device__ __half g_vt   [2 * NHEADS * DHEAD * NSEQ];   // V transposed [b][h][d][n]
__device__ __half g_attn [NTOK * DIMC];
__device__ __half g_w1t  [FWP  * DIMC];
__device__ __half g_w2t  [DIMC * 2 * DIMC];
__device__ __half g_waor [DIMC * DIMC];
__device__ __half g_wmor [HIDPAD * DIMC];
__device__ __half g_wfa  [DIMC * DIMC];
__device__ __half g_wfm  [DIMC * HIDPAD];
__device__ float  g_beff [DIMC];
__device__ float  g_beffp[NSLICE * DIMC];

// ================= helpers =================
__device__ __forceinline__ uint32_t smem_u32(const void* p) {
    uint32_t a;
    asm("{ .reg .u64 t; cvta.to.shared.u64 t, %1; cvt.u32.u64 %0, t; }" : "=r"(a) : "l"(p));
    return a;
}
__device__ __forceinline__ void mma_f16(float& d0, float& d1, float& d2, float& d3,
                                        uint32_t a0, uint32_t a1, uint32_t a2, uint32_t a3,
                                        uint32_t b0, uint32_t b1)
{
    asm volatile(
        "mma.sync.aligned.m16n8k16.row.col.f32.f16.f16.f32 "
        "{%0,%1,%2,%3}, {%4,%5,%6,%7}, {%8,%9}, {%0,%1,%2,%3};"
        : "+f"(d0), "+f"(d1), "+f"(d2), "+f"(d3)
        : "r"(a0), "r"(a1), "r"(a2), "r"(a3), "r"(b0), "r"(b1));
}
__device__ __forceinline__ void ldsm4(uint32_t& r0, uint32_t& r1, uint32_t& r2, uint32_t& r3,
                                      uint32_t addr)
{
    asm volatile("ldmatrix.sync.aligned.m8n8.x4.shared.b16 {%0,%1,%2,%3}, [%4];"
                 : "=r"(r0), "=r"(r1), "=r"(r2), "=r"(r3) : "r"(addr));
}
__device__ __forceinline__ void stsm4(uint32_t addr, uint32_t r0, uint32_t r1,
                                      uint32_t r2, uint32_t r3)
{
    asm volatile("stmatrix.sync.aligned.m8n8.x4.shared.b16 [%0], {%1,%2,%3,%4};"
                 :: "r"(addr), "r"(r0), "r"(r1), "r"(r2), "r"(r3) : "memory");
}
__device__ __forceinline__ float gelu1(float x) {
    float u = 0.7978845608028654f * (x + 0.044715f * x * x * x);
    return 0.5f * x * (1.f + tanhf(u));
}
__device__ __forceinline__ uint32_t h2pack(float a, float b) {
    __half2 h = __floats2half2_rn(a, b);
    return *reinterpret_cast<uint32_t*>(&h);
}
__device__ __forceinline__ uint32_t h2exp2(uint32_t v) {
    uint32_t r; asm("ex2.approx.f16x2 %0, %1;" : "=r"(r) : "r"(v)); return r;
}
__device__ __forceinline__ uint32_t h2minc(uint32_t v, uint32_t c) {
    __half2 a = *reinterpret_cast<__half2*>(&v);
    __half2 b = *reinterpret_cast<__half2*>(&c);
    __half2 m = __hmin2(a, b);
    return *reinterpret_cast<uint32_t*>(&m);
}
#define CP_CA(dst, src) asm volatile("cp.async.ca.shared.global [%0], [%1], 16;" :: "r"(dst), "l"(src) : "memory")
#define CP_CG(dst, src) asm volatile("cp.async.cg.shared.global [%0], [%1], 16;" :: "r"(dst), "l"(src) : "memory")
#define CP_COMMIT()     asm volatile("cp.async.commit_group;" ::: "memory")
#define CP_WAIT(n)      asm volatile("cp.async.wait_group %0;" :: "n"(n) : "memory")

// ============================================================
// prep_w1: W1 [1024 x 3788] -> w1t [3840][1024] (half), 3840 blocks
// ============================================================
__global__ void prep_w1_kernel(const float* __restrict__ W1)
{
    __shared__ float t[32][33];
    int bid = blockIdx.x, tid = threadIdx.x;
    int tx = tid & 31, ty = tid >> 5;
    int bx = bid % (FWP / 32), by = bid / (FWP / 32);
    int n0 = bx * 32, k0 = by * 32;
    #pragma unroll
    for (int i = 0; i < 32; i += 8) {
        int n = n0 + tx;
        t[ty + i][tx] = (n < FW) ? W1[(size_t)(k0 + ty + i) * FW + n] : 0.f;
    }
    __syncthreads();
    #pragma unroll
    for (int i = 0; i < 32; i += 8)
        g_w1t[(size_t)(n0 + ty + i) * DIMC + k0 + tx] = __float2half(t[tx][ty + i]);
}

// ============================================================
// prep_rest: W2^T, Wao copy, Wmo copy(pad), beff partials — 9280 blocks
// ============================================================
__global__ void prep_rest_kernel(const float* __restrict__ W2,
                                 const float* __restrict__ Wao,
                                 const float* __restrict__ Wmo,
                                 const float* __restrict__ bao,
                                 const float* __restrict__ bmo,
                                 const float* __restrict__ b2)
{
    __shared__ float t[32][33];
    int bid = blockIdx.x, tid = threadIdx.x;
    int tx = tid & 31, ty = tid >> 5;

    if (bid < 2048) {
        int bx = bid % 32, by = bid / 32;
        int n0 = bx * 32, k0 = by * 32;
        #pragma unroll
        for (int i = 0; i < 32; i += 8)
            t[ty + i][tx] = W2[(size_t)(k0 + ty + i) * DIMC + n0 + tx];
        __syncthreads();
        #pragma unroll
        for (int i = 0; i < 32; i += 8)
            g_w2t[(size_t)(n0 + ty + i) * 2 * DIMC + k0 + tx] = __float2half(t[tx][ty + i]);
    } else if (bid < 6144) {
        int idx = (bid - 2048) * 256 + tid;
        g_waor[idx] = __float2half(Wao[idx]);
    } else if (bid < 9216) {
        int idx = (bid - 6144) * 256 + tid;
        int r = idx >> 10, c = idx & 1023;
        g_wmor[idx] = (r < MLPHID) ? __float2half(Wmo[(size_t)r * DIMC + c])
                                   : __float2half(0.f);
    } else {
        int b = bid - 9216;
        int n = (b & 3) * 256 + tid;
        int s = b >> 2;
        float acc = (s == 0) ? b2[n] : 0.f;
        int k0 = s * (2048 / NSLICE), k1 = k0 + (2048 / NSLICE);
        for (int k = k0; k < k1; k++) {
            float c = (k < 1024) ? bao[k] : bmo[k - 1024];
            acc += c * W2[(size_t)k * DIMC + n];
        }
        g_beffp[s * DIMC + n] = acc;
    }
}

// ============================================================
// merged fold launch: BOTH weight folds + beff reduce, one wave.
// ============================================================
#define SSTRW 36
#define ABUFW (128 * SSTRW)
#define STAGEW (2 * ABUFW)
#define GEMM_SMEM (3 * STAGEW * 4)   // 110592 B

__global__ void __launch_bounds__(256, 2)
fold_kernel()
{
    extern __shared__ uint32_t smw[];
    int bid = blockIdx.x, tid = threadIdx.x;

    if (bid >= 112) {
        int n = (bid - 112) * 256 + tid;
        float s = 0.f;
        #pragma unroll
        for (int i = 0; i < NSLICE; i++) s += g_beffp[i * DIMC + n];
        g_beff[n] = s;
        return;
    }

    const __half* A; const __half* Bt; __half* C;
    int lda, ldb, ldc, bm, bn;
    if (bid < 64) {
        A = g_w2t;  lda = 2 * DIMC; Bt = g_waor; ldb = DIMC;
        C = g_wfa;  ldc = DIMC;
        bn = (bid & 7) * 128; bm = (bid >> 3) * 128;
    } else {
        int b = bid - 64;
        A = g_w2t + DIMC; lda = 2 * DIMC; Bt = g_wmor; ldb = DIMC;
        C = g_wfm; ldc = HIDPAD;
        bn = (b % 6) * 128; bm = (b / 6) * 128;
    }

    uint32_t sbase = smem_u32(smw);
    int wid = tid >> 5, lane = tid & 31;
    int quad = lane >> 2, tig = lane & 3;
    int wm = (wid & 1) * 64, wn = (wid >> 1) * 32;
    int lr = tid >> 3, lcw = (tid & 7) * 4;
    int lane15 = lane & 15;

    float acc[4][4][4];
    #pragma unroll
    for (int i = 0; i < 4; i++)
        #pragma unroll
        for (int j = 0; j < 4; j++)
            #pragma unroll
            for (int r = 0; r < 4; r++) acc[i][j][r] = 0.f;

    uint32_t aoff[4];
    #pragma unroll
    for (int mt = 0; mt < 4; mt++)
        aoff[mt] = (uint32_t)((wm + mt * 16 + lane15) * SSTRW) * 4 + (lane >> 4) * 16;
    uint32_t boff0 = (uint32_t)((wn + ((lane >> 4) << 3) + (lane & 7)) * SSTRW) * 4
                   + ((lane >> 3) & 1) * 16;
    uint32_t boff1 = boff0 + 16 * SSTRW * 4;

    const int nk = DIMC >> 6;     // 16

    auto prefetch = [&](int it, int st) {
        int k0 = it << 6;
        uint32_t dA = sbase + (uint32_t)st * STAGEW * 4;
        uint32_t dB = dA + ABUFW * 4;
        #pragma unroll
        for (int i = 0; i < 4; i++) {
            int r = i * 32 + lr;
            CP_CG(dA + (uint32_t)(r * SSTRW + lcw) * 4, A + (size_t)(bm + r) * lda + k0 + lcw * 2);
            CP_CG(dB + (uint32_t)(r * SSTRW + lcw) * 4, Bt + (size_t)(bn + r) * ldb + k0 + lcw * 2);
        }
        CP_COMMIT();
    };

    prefetch(0, 0);
    prefetch(1, 1);

    for (int it = 0; it < nk; it++) {
        if (it == nk - 1) { CP_WAIT(0); } else { CP_WAIT(1); }
        __syncthreads();

        uint32_t stA = sbase + (uint32_t)(it % 3) * STAGEW * 4;
        uint32_t stB = stA + ABUFW * 4;
        #pragma unroll
        for (int kk = 0; kk < 4; kk++) {
            uint32_t af[4][4], bf[4][2];
            #pragma unroll
            for (int mt = 0; mt < 4; mt++)
                ldsm4(af[mt][0], af[mt][1], af[mt][2], af[mt][3],
                      stA + aoff[mt] + kk * 32);
            ldsm4(bf[0][0], bf[0][1], bf[1][0], bf[1][1], stB + boff0 + kk * 32);
            ldsm4(bf[2][0], bf[2][1], bf[3][0], bf[3][1], stB + boff1 + kk * 32);
            #pragma unroll
            for (int mt = 0; mt < 4; mt++)
                #pragma unroll
                for (int nt = 0; nt < 4; nt++)
                    mma_f16(acc[mt][nt][0], acc[mt][nt][1],
                            acc[mt][nt][2], acc[mt][nt][3],
                            af[mt][0], af[mt][1], af[mt][2], af[mt][3],
                            bf[nt][0], bf[nt][1]);
        }
        if (it + 2 < nk) prefetch(it + 2, (it + 2) % 3);
    }

    #pragma unroll
    for (int mt = 0; mt < 4; mt++) {
        int r0 = bm + wm + mt * 16 + quad;
        #pragma unroll
        for (int nt = 0; nt < 4; nt++) {
            int c = bn + wn + nt * 8 + tig * 2;
            *reinterpret_cast<uint32_t*>(C + (size_t)r0 * ldc + c) =
                h2pack(acc[mt][nt][0], acc[mt][nt][1]);
            *reinterpret_cast<uint32_t*>(C + (size_t)(r0 + 8) * ldc + c) =
                h2pack(acc[mt][nt][2], acc[mt][nt][3]);
        }
    }
}

// ============================================================
// LayerNorm over DIM=1024, half output
// ============================================================
__global__ void ln_kernel(const float* __restrict__ x,
                          const float* __restrict__ g,
                          const float* __restrict__ b,
                          __half* __restrict__ out)
{
    int row = blockIdx.x;
    int tid = threadIdx.x;
    const float4 v = reinterpret_cast<const float4*>(x + (size_t)row * DIMC)[tid];

    float s  = v.x + v.y + v.z + v.w;
    float sq = v.x*v.x + v.y*v.y + v.z*v.z + v.w*v.w;
    #pragma unroll
    for (int o = 16; o > 0; o >>= 1) {
        s  += __shfl_xor_sync(0xffffffffu, s,  o);
        sq += __shfl_xor_sync(0xffffffffu, sq, o);
    }
    __shared__ float ws[8], wq[8];
    int warp = tid >> 5, lane = tid & 31;
    if (lane == 0) { ws[warp] = s; wq[warp] = sq; }
    __syncthreads();
    if (warp == 0) {
        float s2  = (lane < 8) ? ws[lane] : 0.f;
        float sq2 = (lane < 8) ? wq[lane] : 0.f;
        #pragma unroll
        for (int o = 4; o > 0; o >>= 1) {
            s2  += __shfl_xor_sync(0xffffffffu, s2,  o);
            sq2 += __shfl_xor_sync(0xffffffffu, sq2, o);
        }
        if (lane == 0) { ws[0] = s2; wq[0] = sq2; }
    }
    __syncthreads();
    float mean = ws[0] * (1.f / DIMC);
    float var  = wq[0] * (1.f / DIMC) - mean * mean;
    float rstd = rsqrtf(var + LN_EPS);

    float4 gg = reinterpret_cast<const float4*>(g)[tid];
    float4 bb = reinterpret_cast<const float4*>(b)[tid];
    uint2 o2;
    o2.x = h2pack((v.x - mean) * rstd * gg.x + bb.x,
                  (v.y - mean) * rstd * gg.y + bb.y);
    o2.y = h2pack((v.z - mean) * rstd * gg.z + bb.z,
                  (v.w - mean) * rstd * gg.w + bb.w);
    reinterpret_cast<uint2*>(out + (size_t)row * DIMC)[tid] = o2;
}

// ============================================================
// fp16 mma.sync GEMM, 3-stage cp.async pipeline, ldmatrix frags.
// mode 1: GEMM1-qkv — region 0 (qk): fused per-head LN (+log2 q scale)
//                     region 1: V->g_vt transposed
// mode 3: GEMM1-mlp slice: gelu epilogue, half out
// mode 2: C float + bias + resid (apply)    mode 0: plain half out
// ============================================================
__global__ void __launch_bounds__(256, 2)
mma_gemm(const __half* __restrict__ A, int lda,
         const __half* __restrict__ Bt, int ldb, int K1,
         const __half* __restrict__ A2, int lda2,
         const __half* __restrict__ Bt2, int ldb2, int K2,
         __half* __restrict__ Ch, int ldch,
         float* __restrict__ Cf, int ldcf,
         const float* __restrict__ bias, int nbias,
         const float* __restrict__ resid, int ldr,
         const float* __restrict__ qg, const float* __restrict__ qb,
         const float* __restrict__ kg, const float* __restrict__ kb,
         int mrow0, int mode)
{
    extern __shared__ uint32_t smw[];
    uint32_t sbase = smem_u32(smw);
    int tid  = threadIdx.x;
    int wid  = tid >> 5, lane = tid & 31;
    int quad = lane >> 2, tig = lane & 3;
    int bm = blockIdx.y * 128 + mrow0, bn = blockIdx.x * 128;
    int wm = (wid & 1) * 64, wn = (wid >> 1) * 32;

    float acc[4][4][4];
    #pragma unroll
    for (int i = 0; i < 4; i++)
        #pragma unroll
        for (int j = 0; j < 4; j++)
            #pragma unroll
            for (int r = 0; r < 4; r++) acc[i][j][r] = 0.f;

    int lr = tid >> 3;
    int lcw = (tid & 7) * 4;

    int lane15 = lane & 15;
    uint32_t aoff[4];
    #pragma unroll
    for (int mt = 0; mt < 4; mt++)
        aoff[mt] = (uint32_t)((wm + mt * 16 + lane15) * SSTRW) * 4 + (lane >> 4) * 16;
    uint32_t boff0 = (uint32_t)((wn + ((lane >> 4) << 3) + (lane & 7)) * SSTRW) * 4
                   + ((lane >> 3) & 1) * 16;
    uint32_t boff1 = boff0 + 16 * SSTRW * 4;

    const int nk1 = K1 >> 6;
    const int nk  = nk1 + (K2 >> 6);

    auto prefetch = [&](int it, int st) {
        const __half* Ab; const __half* Bb; int la, lb, k0;
        if (it < nk1) { Ab = A;  Bb = Bt;  la = lda;  lb = ldb;  k0 = it << 6; }
        else          { Ab = A2; Bb = Bt2; la = lda2; lb = ldb2; k0 = (it - nk1) << 6; }
        uint32_t dA = sbase + (uint32_t)st * STAGEW * 4;
        uint32_t dB = dA + ABUFW * 4;
        #pragma unroll
        for (int i = 0; i < 4; i++) {
            int r = i * 32 + lr;
            CP_CG(dA + (uint32_t)(r * SSTRW + lcw) * 4, Ab + (size_t)(bm + r) * la + k0 + lcw * 2);
            CP_CG(dB + (uint32_t)(r * SSTRW + lcw) * 4, Bb + (size_t)(bn + r) * lb + k0 + lcw * 2);
        }
        CP_COMMIT();
    };

    prefetch(0, 0);
    if (nk > 1) prefetch(1, 1);

    for (int it = 0; it < nk; it++) {
        if (it == nk - 1) { CP_WAIT(0); } else { CP_WAIT(1); }
        __syncthreads();

        uint32_t stA = sbase + (uint32_t)(it % 3) * STAGEW * 4;
        uint32_t stB = stA + ABUFW * 4;

        #pragma unroll
        for (int kk = 0; kk < 4; kk++) {
            uint32_t af[4][4], bf[4][2];
            #pragma unroll
            for (int mt = 0; mt < 4; mt++)
                ldsm4(af[mt][0], af[mt][1], af[mt][2], af[mt][3],
                      stA + aoff[mt] + kk * 32);
            ldsm4(bf[0][0], bf[0][1], bf[1][0], bf[1][1], stB + boff0 + kk * 32);
            ldsm4(bf[2][0], bf[2][1], bf[3][0], bf[3][1], stB + boff1 + kk * 32);
            #pragma unroll
            for (int mt = 0; mt < 4; mt++)
                #pragma unroll
                for (int nt = 0; nt < 4; nt++)
                    mma_f16(acc[mt][nt][0], acc[mt][nt][1],
                            acc[mt][nt][2], acc[mt][nt][3],
                            af[mt][0], af[mt][1], af[mt][2], af[mt][3],
                            bf[nt][0], bf[nt][1]);
        }
        if (it + 2 < nk) prefetch(it + 2, (it + 2) % 3);
    }
    __syncthreads();   // protect smem reuse in region-0 epilogue

    int region = (mode != 1) ? -1 : ((bn < 2 * DIMC) ? 0 : 1);

    if (region == 0) {
        float* ssum = reinterpret_cast<float*>(smw);       // [128][4]
        float* ssq  = ssum + 128 * 4;                      // [128][4]
        int ch = wn >> 5;

        #pragma unroll
        for (int mt = 0; mt < 4; mt++) {
            float slo = 0.f, sqlo = 0.f, shi = 0.f, sqhi = 0.f;
            #pragma unroll
            for (int nt = 0; nt < 4; nt++) {
                int c = bn + wn + nt * 8 + tig * 2;
                float b0 = bias[c], b1v = bias[c + 1];
                acc[mt][nt][0] += b0; acc[mt][nt][1] += b1v;
                acc[mt][nt][2] += b0; acc[mt][nt][3] += b1v;
                slo  += acc[mt][nt][0] + acc[mt][nt][1];
                sqlo += acc[mt][nt][0] * acc[mt][nt][0] + acc[mt][nt][1] * acc[mt][nt][1];
                shi  += acc[mt][nt][2] + acc[mt][nt][3];
                sqhi += acc[mt][nt][2] * acc[mt][nt][2] + acc[mt][nt][3] * acc[mt][nt][3];
            }
            slo  += __shfl_xor_sync(0xffffffffu, slo, 1);
            slo  += __shfl_xor_sync(0xffffffffu, slo, 2);
            sqlo += __shfl_xor_sync(0xffffffffu, sqlo, 1);
            sqlo += __shfl_xor_sync(0xffffffffu, sqlo, 2);
            shi  += __shfl_xor_sync(0xffffffffu, shi, 1);
            shi  += __shfl_xor_sync(0xffffffffu, shi, 2);
            sqhi += __shfl_xor_sync(0xffffffffu, sqhi, 1);
            sqhi += __shfl_xor_sync(0xffffffffu, sqhi, 2);
            if (tig == 0) {
                int rl = wm + mt * 16 + quad;
                ssum[rl * 4 + ch] = slo;        ssq[rl * 4 + ch] = sqlo;
                ssum[(rl + 8) * 4 + ch] = shi;  ssq[(rl + 8) * 4 + ch] = sqhi;
            }
        }
        __syncthreads();

        int hb = (wn >> 6) << 1;
        bool isq = (bn < DIMC);
        const float* gv = isq ? qg : kg;
        const float* bv = isq ? qb : kb;
        float qsc = isq ? QSCALE : 1.f;

        #pragma unroll
        for (int mt = 0; mt < 4; mt++) {
            int rl = wm + mt * 16 + quad;
            float mlo = (ssum[rl * 4 + hb] + ssum[rl * 4 + hb + 1]) * (1.f / 64.f);
            float vlo = (ssq[rl * 4 + hb] + ssq[rl * 4 + hb + 1]) * (1.f / 64.f) - mlo * mlo;
            float rlo = rsqrtf(vlo + LN_EPS);
            float mhi = (ssum[(rl + 8) * 4 + hb] + ssum[(rl + 8) * 4 + hb + 1]) * (1.f / 64.f);
            float vhi = (ssq[(rl + 8) * 4 + hb] + ssq[(rl + 8) * 4 + hb + 1]) * (1.f / 64.f) - mhi * mhi;
            float rhi = rsqrtf(vhi + LN_EPS);
            int r0 = bm + rl;
            #pragma unroll
            for (int nt = 0; nt < 4; nt++) {
                int c = bn + wn + nt * 8 + tig * 2;
                int d = c & 63;
                float g0 = gv[d], g1 = gv[d + 1];
                float e0 = bv[d], e1 = bv[d + 1];
                float o0 = ((acc[mt][nt][0] - mlo) * rlo * g0 + e0) * qsc;
                float o1 = ((acc[mt][nt][1] - mlo) * rlo * g1 + e1) * qsc;
                float o2 = ((acc[mt][nt][2] - mhi) * rhi * g0 + e0) * qsc;
                float o3 = ((acc[mt][nt][3] - mhi) * rhi * g1 + e1) * qsc;
                *reinterpret_cast<uint32_t*>(Ch + (size_t)r0 * ldch + c) = h2pack(o0, o1);
                *reinterpret_cast<uint32_t*>(Ch + (size_t)(r0 + 8) * ldch + c) = h2pack(o2, o3);
            }
        }
        return;
    }

    #pragma unroll
    for (int mt = 0; mt < 4; mt++) {
        int r0 = bm + wm + mt * 16 + quad;
        #pragma unroll
        for (int nt = 0; nt < 4; nt++) {
            int c = bn + wn + nt * 8 + tig * 2;
            float2 v0 = make_float2(acc[mt][nt][0], acc[mt][nt][1]);
            float2 v1 = make_float2(acc[mt][nt][2], acc[mt][nt][3]);
            if (bias) {
                float bx = (c     < nbias) ? bias[c]     : 0.f;
                float by = (c + 1 < nbias) ? bias[c + 1] : 0.f;
                v0.x += bx; v0.y += by;
                v1.x += bx; v1.y += by;
            }
            if (mode == 2) {
                float2 ra = *reinterpret_cast<const float2*>(resid + (size_t)r0 * ldr + c);
                float2 rb = *reinterpret_cast<const float2*>(resid + (size_t)(r0 + 8) * ldr + c);
                v0.x += ra.x; v0.y += ra.y;
                v1.x += rb.x; v1.y += rb.y;
                *reinterpret_cast<float2*>(Cf + (size_t)r0 * ldcf + c) = v0;
                *reinterpret_cast<float2*>(Cf + (size_t)(r0 + 8) * ldcf + c) = v1;
            } else if (region == 1) {
                int d = c - 2 * DIMC;
                int hh = d >> 6, dd = d & 63;
                int bbk = r0 >> 11, nn = r0 & 2047;
                size_t base = ((size_t)(bbk * NHEADS + hh) * DHEAD);
                g_vt[(base + dd    ) * NSEQ + nn    ] = __float2half(v0.x);
                g_vt[(base + dd + 1) * NSEQ + nn    ] = __float2half(v0.y);
                g_vt[(base + dd    ) * NSEQ + nn + 8] = __float2half(v1.x);
                g_vt[(base + dd + 1) * NSEQ + nn + 8] = __float2half(v1.y);
            } else {
                if (mode == 3) {
                    v0.x = gelu1(v0.x); v0.y = gelu1(v0.y);
                    v1.x = gelu1(v1.x); v1.y = gelu1(v1.y);
                }
                *reinterpret_cast<uint32_t*>(Ch + (size_t)r0 * ldch + c) = h2pack(v0.x, v0.y);
                *reinterpret_cast<uint32_t*>(Ch + (size_t)(r0 + 8) * ldch + c) = h2pack(v1.x, v1.y);
            }
        }
    }
}

// ============================================================
// Flash attention: fp16 m16n8k16, no online max (LN-bounded scores),
// p = 2^s via ex2.approx.f16x2 (log2e folded into q), row-sum l via
// one extra MMA against an all-ones B fragment.
// ============================================================
#define KSTRW 36
#define QWORDS (128 * KSTRW)
#define KVWORDS (64 * KSTRW)
#define ATTN_SMEM ((QWORDS + 4 * KVWORDS) * 4)   // 55296 B
#define ONESF  0x3C003C00u
#define CLAMP2 0x4BC04BC0u   // half2(15.5); score bound is ~13.3

__global__ void __launch_bounds__(256, 2)
fattn_kernel(const __half* __restrict__ fused, __half* __restrict__ aout, int bbase)
{
    extern __shared__ uint32_t smw[];
    uint32_t sbase = smem_u32(smw);

    int tid  = threadIdx.x;
    int wid  = tid >> 5, lane = tid & 31;
    int quad = lane >> 2, tig = lane & 3;
    int lane15 = lane & 15;
    int h  = blockIdx.y;
    int bb = blockIdx.z + bbase;
    int q0 = blockIdx.x * 128;
    int tq0 = bb * NSEQ + q0;
    int kvb = bb * NSEQ;
    const __half* vtb = g_vt + (size_t)(bb * NHEADS + h) * DHEAD * NSEQ;

    auto prefetch_kv = [&](int kt, int buf) {
        uint32_t dK = sbase + (uint32_t)(QWORDS + buf * 2 * KVWORDS) * 4;
        uint32_t dV = dK + KVWORDS * 4;
        #pragma unroll
        for (int i = 0; i < 2; i++) {
            int idx = i * 256 + tid;
            int r = idx >> 3, chh = (idx & 7) * 8;
            CP_CG(dK + (uint32_t)(r * KSTRW + chh / 2) * 4,
                  fused + (size_t)(kvb + kt + r) * FWP + DIMC + h * DHEAD + chh);
            CP_CG(dV + (uint32_t)(r * KSTRW + chh / 2) * 4,
                  vtb + (size_t)r * NSEQ + kt + chh);
        }
        CP_COMMIT();
    };

    #pragma unroll
    for (int i = 0; i < 4; i++) {
        int idx = i * 256 + tid;
        int r = idx >> 3, chh = (idx & 7) * 8;
        CP_CA(sbase + (uint32_t)(r * KSTRW + chh / 2) * 4,
              fused + (size_t)(tq0 + r) * FWP + h * DHEAD + chh);
    }
    prefetch_kv(0, 0);
    CP_WAIT(0);
    __syncthreads();

    uint32_t aPat = (uint32_t)(lane15 * KSTRW) * 4 + (lane >> 4) * 16;
    uint32_t bPat = (uint32_t)((((lane >> 4) << 3) + (lane & 7)) * KSTRW) * 4
                  + ((lane >> 3) & 1) * 16;
    uint32_t sPat = (uint32_t)(((((lane >> 3) & 1) << 3) + (lane & 7)) * KSTRW) * 4
                  + (lane >> 4) * 16;

    uint32_t qf[4][4];
    {
        uint32_t qbase = sbase + (uint32_t)(wid * 16 * KSTRW) * 4 + aPat;
        #pragma unroll
        for (int kc = 0; kc < 4; kc++)
            ldsm4(qf[kc][0], qf[kc][1], qf[kc][2], qf[kc][3], qbase + kc * 32);
    }
    uint32_t pBase = sbase + (uint32_t)(wid * 16 * KSTRW) * 4;

    float o[8][4];
    #pragma unroll
    for (int i = 0; i < 8; i++)
        #pragma unroll
        for (int j = 0; j < 4; j++) o[i][j] = 0.f;
    float ls[4] = {0.f, 0.f, 0.f, 0.f};

    for (int t = 0; t < NSEQ / 64; t++) {
        int b = t & 1;
        if (t + 1 < NSEQ / 64) prefetch_kv((t + 1) * 64, b ^ 1);

        uint32_t kBase = sbase + (uint32_t)(QWORDS + b * 2 * KVWORDS) * 4;
        uint32_t vBase = kBase + KVWORDS * 4;

        float sc[8][4];
        #pragma unroll
        for (int i = 0; i < 8; i++)
            #pragma unroll
            for (int j = 0; j < 4; j++) sc[i][j] = 0.f;

        #pragma unroll
        for (int kc = 0; kc < 4; kc++) {
            #pragma unroll
            for (int np = 0; np < 4; np++) {
                uint32_t b00, b01, b10, b11;
                ldsm4(b00, b01, b10, b11,
                      kBase + (uint32_t)(np * 16 * KSTRW) * 4 + bPat + kc * 32);
                mma_f16(sc[2*np][0], sc[2*np][1], sc[2*np][2], sc[2*np][3],
                        qf[kc][0], qf[kc][1], qf[kc][2], qf[kc][3], b00, b01);
                mma_f16(sc[2*np+1][0], sc[2*np+1][1], sc[2*np+1][2], sc[2*np+1][3],
                        qf[kc][0], qf[kc][1], qf[kc][2], qf[kc][3], b10, b11);
            }
        }

        uint32_t hl0[8], hl1[8];
        #pragma unroll
        for (int nf = 0; nf < 8; nf++) {
            hl0[nf] = h2exp2(h2minc(h2pack(sc[nf][0], sc[nf][1]), CLAMP2));
            hl1[nf] = h2exp2(h2minc(h2pack(sc[nf][2], sc[nf][3]), CLAMP2));
        }
        #pragma unroll
        for (int np = 0; np < 4; np++)
            stsm4(pBase + sPat + np * 32,
                  hl0[2*np], hl1[2*np], hl0[2*np+1], hl1[2*np+1]);
        __syncwarp();

        #pragma unroll
        for (int kc = 0; kc < 4; kc++) {
            uint32_t a0, a1, a2, a3;
            ldsm4(a0, a1, a2, a3, pBase + aPat + kc * 32);
            mma_f16(ls[0], ls[1], ls[2], ls[3], a0, a1, a2, a3, ONESF, ONESF);
            #pragma unroll
            for (int np = 0; np < 4; np++) {
                uint32_t b00, b01, b10, b11;
                ldsm4(b00, b01, b10, b11,
                      vBase + (uint32_t)(np * 16 * KSTRW) * 4 + bPat + kc * 32);
                mma_f16(o[2*np][0], o[2*np][1], o[2*np][2], o[2*np][3],
                        a0, a1, a2, a3, b00, b01);
                mma_f16(o[2*np+1][0], o[2*np+1][1], o[2*np+1][2], o[2*np+1][3],
                        a0, a1, a2, a3, b10, b11);
            }
        }
        __syncwarp();

        if (t + 1 < NSEQ / 64) { CP_WAIT(0); }
        __syncthreads();
    }

    float il0 = 1.f / ls[0], il1 = 1.f / ls[2];
    int r0 = tq0 + wid * 16 + quad;
    #pragma unroll
    for (int nf = 0; nf < 8; nf++) {
        int c = h * DHEAD + nf * 8 + tig * 2;
        *reinterpret_cast<uint32_t*>(aout + (size_t)r0 * DIMC + c) =
            h2pack(o[nf][0] * il0, o[nf][1] * il0);
        *reinterpret_cast<uint32_t*>(aout + (size_t)(r0 + 8) * DIMC + c) =
            h2pack(o[nf][2] * il1, o[nf][3] * il1);
    }
}

// ============================================================
// launch — R12 schedule + apply split (apply_m overlaps fattn)
// ============================================================
extern "C" void kernel_launch(void* const* d_in, const int* in_sizes, int n_in,
                              void* d_out, int out_size)
{
    const float* x      = (const float*)d_in[0];
    const float* norm_g = (const float*)d_in[1];
    const float* norm_b = (const float*)d_in[2];
    const float* W1     = (const float*)d_in[3];
    const float* b1     = (const float*)d_in[4];
    const float* qn_g   = (const float*)d_in[5];
    const float* qn_b   = (const float*)d_in[6];
    const float* kn_g   = (const float*)d_in[7];
    const float* kn_b   = (const float*)d_in[8];
    const float* Wao    = (const float*)d_in[9];
    const float* bao    = (const float*)d_in[10];
    const float* Wmo    = (const float*)d_in[11];
    const float* bmo    = (const float*)d_in[12];
    const float* W2     = (const float*)d_in[13];
    const float* b2     = (const float*)d_in[14];
    float*       out    = (float*)d_out;

    __half *norm, *fused, *attn, *w1t, *wfa, *wfm;
    float *beff;
    cudaGetSymbolAddress((void**)&norm,  g_norm);
    cudaGetSymbolAddress((void**)&fused, g_fused);
    cudaGetSymbolAddress((void**)&attn,  g_attn);
    cudaGetSymbolAddress((void**)&w1t,   g_w1t);
    cudaGetSymbolAddress((void**)&wfa,   g_wfa);
    cudaGetSymbolAddress((void**)&wfm,   g_wfm);
    cudaGetSymbolAddress((void**)&beff,  g_beff);

    static bool inited = false;
    static cudaStream_t s2;
    static cudaEvent_t ev1, evw1, evg1, evm;
    if (!inited) {
        cudaStreamCreateWithFlags(&s2, cudaStreamNonBlocking);
        cudaEventCreateWithFlags(&ev1, cudaEventDisableTiming);
        cudaEventCreateWithFlags(&evw1, cudaEventDisableTiming);
        cudaEventCreateWithFlags(&evg1, cudaEventDisableTiming);
        cudaEventCreateWithFlags(&evm, cudaEventDisableTiming);
        cudaFuncSetAttribute(mma_gemm, cudaFuncAttributeMaxDynamicSharedMemorySize, GEMM_SMEM);
        cudaFuncSetAttribute(fold_kernel, cudaFuncAttributeMaxDynamicSharedMemorySize, GEMM_SMEM);
        cudaFuncSetAttribute(fattn_kernel, cudaFuncAttributeMaxDynamicSharedMemorySize, ATTN_SMEM);
        inited = true;
    }

    // ---- fork: side chain (prep_w1 -> prep_rest -> fold), later mlp + apply_m
    cudaEventRecord(ev1, 0);
    cudaStreamWaitEvent(s2, ev1, 0);
    prep_w1_kernel<<<3840, 256, 0, s2>>>(W1);
    cudaEventRecord(evw1, s2);
    prep_rest_kernel<<<9280, 256, 0, s2>>>(W2, Wao, Wmo, bao, bmo, b2);
    fold_kernel<<<116, 256, GEMM_SMEM, s2>>>();

    // ---- main chain: ln concurrent with prep_w1
    ln_kernel<<<NTOK, 256>>>(x, norm_g, norm_b, norm);
    cudaStreamWaitEvent(0, evw1, 0);

    // GEMM1-qkv (cols 0..3071): qk->LN'd fused, V->g_vt transposed
    mma_gemm<<<dim3(24, NTOK / 128), 256, GEMM_SMEM>>>(
        norm, DIMC, w1t, DIMC, DIMC,
        nullptr, 0, nullptr, 0, 0,
        fused, FWP, nullptr, 0, b1, FW, nullptr, 0,
        qn_g, qn_b, kn_g, kn_b, 0, 1);
    cudaEventRecord(evg1, 0);

    // side stream: GEMM1-mlp slice (cols 3072.., gelu) overlaps fattn
    cudaStreamWaitEvent(s2, evg1, 0);
    mma_gemm<<<dim3(6, NTOK / 128), 256, GEMM_SMEM, s2>>>(
        norm, DIMC, w1t + (size_t)(3 * DIMC) * DIMC, DIMC, DIMC,
        nullptr, 0, nullptr, 0, 0,
        fused + 3 * DIMC, FWP, nullptr, 0, b1 + 3 * DIMC, FW - 3 * DIMC, nullptr, 0,
        nullptr, nullptr, nullptr, nullptr, 0, 3);
    // side stream: apply_m: out = x + beff + gelu_hidden @ wfm^T  (overlaps fattn)
    mma_gemm<<<dim3(DIMC / 128, NTOK / 128), 256, GEMM_SMEM, s2>>>(
        fused + 3 * DIMC, FWP, wfm, HIDPAD, HIDPAD,
        nullptr, 0, nullptr, 0, 0,
        nullptr, 0, out, DIMC, beff, DIMC, x, DIMC,
        nullptr, nullptr, nullptr, nullptr, 0, 2);
    cudaEventRecord(evm, s2);

    // flash attention (monolithic, main stream — concurrent with mlp+apply_m)
    fattn_kernel<<<dim3(NSEQ / 128, NHEADS, 2), 256, ATTN_SMEM>>>(fused, attn, 0);

    // ---- join, then apply_a: out += attn @ wfa^T  (K=1024 only)
    cudaStreamWaitEvent(0, evm, 0);
    mma_gemm<<<dim3(DIMC / 128, NTOK / 128), 256, GEMM_SMEM>>>(
        attn, DIMC, wfa, DIMC, DIMC,
        nullptr, 0, nullptr, 0, 0,
        nullptr, 0, out, DIMC, nullptr, 0, out, DIMC,
        nullptr, nullptr, nullptr, nullptr, 0, 2);
}

// round 15
// speedup vs baseline: 1.5620x; 1.0602x over previous
#include <cuda_runtime.h>
#include <cuda_fp16.h>
#include <math.h>
#include <stdint.h>

// ---------------- problem constants ----------------
#define NTOK   4096              // B*N = 2*2048
#define DIMC   1024
#define NHEADS 16
#define DHEAD  64
#define MLPHID 716
#define FW     3788              // 3*DIM + MLP_HID (true width)
#define FWP    3840              // padded to 30*128
#define HIDPAD 768               // Wmo rows padded; K2 of apply
#define NSEQ   2048
#define LN_EPS 1e-6f
#define NSLICE 16
#define QSCALE 0.1803368801111204f   // 0.125 * log2(e): softmax in 2^s domain

// ---------------- scratch (static device globals) ------
__device__ __half g_norm [NTOK * DIMC];
__device__ __half g_fused[NTOK * FWP];
__device__ __half g_vt   [2 * NHEADS * DHEAD * NSEQ];   // V transposed [b][h][d][n]
__device__ __half g_attn [NTOK * DIMC];
__device__ __half g_w1t  [FWP  * DIMC];
__device__ __half g_w2t  [DIMC * 2 * DIMC];
__device__ __half g_waor [DIMC * DIMC];
__device__ __half g_wmor [HIDPAD * DIMC];
__device__ __half g_wfa  [DIMC * DIMC];
__device__ __half g_wfm  [DIMC * HIDPAD];
__device__ float  g_beff [DIMC];
__device__ float  g_beffp[NSLICE * DIMC];

// ================= helpers =================
__device__ __forceinline__ uint32_t smem_u32(const void* p) {
    uint32_t a;
    asm("{ .reg .u64 t; cvta.to.shared.u64 t, %1; cvt.u32.u64 %0, t; }" : "=r"(a) : "l"(p));
    return a;
}
__device__ __forceinline__ void mma_f16(float& d0, float& d1, float& d2, float& d3,
                                        uint32_t a0, uint32_t a1, uint32_t a2, uint32_t a3,
                                        uint32_t b0, uint32_t b1)
{
    asm volatile(
        "mma.sync.aligned.m16n8k16.row.col.f32.f16.f16.f32 "
        "{%0,%1,%2,%3}, {%4,%5,%6,%7}, {%8,%9}, {%0,%1,%2,%3};"
        : "+f"(d0), "+f"(d1), "+f"(d2), "+f"(d3)
        : "r"(a0), "r"(a1), "r"(a2), "r"(a3), "r"(b0), "r"(b1));
}
__device__ __forceinline__ void ldsm4(uint32_t& r0, uint32_t& r1, uint32_t& r2, uint32_t& r3,
                                      uint32_t addr)
{
    asm volatile("ldmatrix.sync.aligned.m8n8.x4.shared.b16 {%0,%1,%2,%3}, [%4];"
                 : "=r"(r0), "=r"(r1), "=r"(r2), "=r"(r3) : "r"(addr));
}
__device__ __forceinline__ void stsm4(uint32_t addr, uint32_t r0, uint32_t r1,
                                      uint32_t r2, uint32_t r3)
{
    asm volatile("stmatrix.sync.aligned.m8n8.x4.shared.b16 [%0], {%1,%2,%3,%4};"
                 :: "r"(addr), "r"(r0), "r"(r1), "r"(r2), "r"(r3) : "memory");
}
__device__ __forceinline__ float gelu1(float x) {
    float u = 0.7978845608028654f * (x + 0.044715f * x * x * x);
    return 0.5f * x * (1.f + tanhf(u));
}
__device__ __forceinline__ uint32_t h2pack(float a, float b) {
    __half2 h = __floats2half2_rn(a, b);
    return *reinterpret_cast<uint32_t*>(&h);
}
__device__ __forceinline__ uint32_t h2exp2(uint32_t v) {
    uint32_t r; asm("ex2.approx.f16x2 %0, %1;" : "=r"(r) : "r"(v)); return r;
}
__device__ __forceinline__ uint32_t h2minc(uint32_t v, uint32_t c) {
    __half2 a = *reinterpret_cast<__half2*>(&v);
    __half2 b = *reinterpret_cast<__half2*>(&c);
    __half2 m = __hmin2(a, b);
    return *reinterpret_cast<uint32_t*>(&m);
}
#define CP_CA(dst, src) asm volatile("cp.async.ca.shared.global [%0], [%1], 16;" :: "r"(dst), "l"(src) : "memory")
#define CP_CG(dst, src) asm volatile("cp.async.cg.shared.global [%0], [%1], 16;" :: "r"(dst), "l"(src) : "memory")
#define CP_COMMIT()     asm volatile("cp.async.commit_group;" ::: "memory")
#define CP_WAIT(n)      asm volatile("cp.async.wait_group %0;" :: "n"(n) : "memory")

// ============================================================
// prep_w1: W1 [1024 x 3788] -> w1t [3840][1024] (half), 3840 blocks
// ============================================================
__global__ void prep_w1_kernel(const float* __restrict__ W1)
{
    __shared__ float t[32][33];
    int bid = blockIdx.x, tid = threadIdx.x;
    int tx = tid & 31, ty = tid >> 5;
    int bx = bid % (FWP / 32), by = bid / (FWP / 32);
    int n0 = bx * 32, k0 = by * 32;
    #pragma unroll
    for (int i = 0; i < 32; i += 8) {
        int n = n0 + tx;
        t[ty + i][tx] = (n < FW) ? W1[(size_t)(k0 + ty + i) * FW + n] : 0.f;
    }
    __syncthreads();
    #pragma unroll
    for (int i = 0; i < 32; i += 8)
        g_w1t[(size_t)(n0 + ty + i) * DIMC + k0 + tx] = __float2half(t[tx][ty + i]);
}

// ============================================================
// prep_rest: W2^T, Wao copy, Wmo copy(pad), beff partials — 9280 blocks
// ============================================================
__global__ void prep_rest_kernel(const float* __restrict__ W2,
                                 const float* __restrict__ Wao,
                                 const float* __restrict__ Wmo,
                                 const float* __restrict__ bao,
                                 const float* __restrict__ bmo,
                                 const float* __restrict__ b2)
{
    __shared__ float t[32][33];
    int bid = blockIdx.x, tid = threadIdx.x;
    int tx = tid & 31, ty = tid >> 5;

    if (bid < 2048) {
        int bx = bid % 32, by = bid / 32;
        int n0 = bx * 32, k0 = by * 32;
        #pragma unroll
        for (int i = 0; i < 32; i += 8)
            t[ty + i][tx] = W2[(size_t)(k0 + ty + i) * DIMC + n0 + tx];
        __syncthreads();
        #pragma unroll
        for (int i = 0; i < 32; i += 8)
            g_w2t[(size_t)(n0 + ty + i) * 2 * DIMC + k0 + tx] = __float2half(t[tx][ty + i]);
    } else if (bid < 6144) {
        int idx = (bid - 2048) * 256 + tid;
        g_waor[idx] = __float2half(Wao[idx]);
    } else if (bid < 9216) {
        int idx = (bid - 6144) * 256 + tid;
        int r = idx >> 10, c = idx & 1023;
        g_wmor[idx] = (r < MLPHID) ? __float2half(Wmo[(size_t)r * DIMC + c])
                                   : __float2half(0.f);
    } else {
        int b = bid - 9216;
        int n = (b & 3) * 256 + tid;
        int s = b >> 2;
        float acc = (s == 0) ? b2[n] : 0.f;
        int k0 = s * (2048 / NSLICE), k1 = k0 + (2048 / NSLICE);
        for (int k = k0; k < k1; k++) {
            float c = (k < 1024) ? bao[k] : bmo[k - 1024];
            acc += c * W2[(size_t)k * DIMC + n];
        }
        g_beffp[s * DIMC + n] = acc;
    }
}

// ============================================================
// merged fold launch: BOTH weight folds + beff reduce, one wave.
// ============================================================
#define SSTRW 36
#define ABUFW (128 * SSTRW)
#define STAGEW (2 * ABUFW)
#define GEMM_SMEM (3 * STAGEW * 4)   // 110592 B

__global__ void __launch_bounds__(256, 2)
fold_kernel()
{
    extern __shared__ uint32_t smw[];
    int bid = blockIdx.x, tid = threadIdx.x;

    if (bid >= 112) {
        int n = (bid - 112) * 256 + tid;
        float s = 0.f;
        #pragma unroll
        for (int i = 0; i < NSLICE; i++) s += g_beffp[i * DIMC + n];
        g_beff[n] = s;
        return;
    }

    const __half* A; const __half* Bt; __half* C;
    int lda, ldb, ldc, bm, bn;
    if (bid < 64) {
        A = g_w2t;  lda = 2 * DIMC; Bt = g_waor; ldb = DIMC;
        C = g_wfa;  ldc = DIMC;
        bn = (bid & 7) * 128; bm = (bid >> 3) * 128;
    } else {
        int b = bid - 64;
        A = g_w2t + DIMC; lda = 2 * DIMC; Bt = g_wmor; ldb = DIMC;
        C = g_wfm; ldc = HIDPAD;
        bn = (b % 6) * 128; bm = (b / 6) * 128;
    }

    uint32_t sbase = smem_u32(smw);
    int wid = tid >> 5, lane = tid & 31;
    int quad = lane >> 2, tig = lane & 3;
    int wm = (wid & 1) * 64, wn = (wid >> 1) * 32;
    int lr = tid >> 3, lcw = (tid & 7) * 4;
    int lane15 = lane & 15;

    float acc[4][4][4];
    #pragma unroll
    for (int i = 0; i < 4; i++)
        #pragma unroll
        for (int j = 0; j < 4; j++)
            #pragma unroll
            for (int r = 0; r < 4; r++) acc[i][j][r] = 0.f;

    uint32_t aoff[4];
    #pragma unroll
    for (int mt = 0; mt < 4; mt++)
        aoff[mt] = (uint32_t)((wm + mt * 16 + lane15) * SSTRW) * 4 + (lane >> 4) * 16;
    uint32_t boff0 = (uint32_t)((wn + ((lane >> 4) << 3) + (lane & 7)) * SSTRW) * 4
                   + ((lane >> 3) & 1) * 16;
    uint32_t boff1 = boff0 + 16 * SSTRW * 4;

    const int nk = DIMC >> 6;     // 16

    auto prefetch = [&](int it, int st) {
        int k0 = it << 6;
        uint32_t dA = sbase + (uint32_t)st * STAGEW * 4;
        uint32_t dB = dA + ABUFW * 4;
        #pragma unroll
        for (int i = 0; i < 4; i++) {
            int r = i * 32 + lr;
            CP_CG(dA + (uint32_t)(r * SSTRW + lcw) * 4, A + (size_t)(bm + r) * lda + k0 + lcw * 2);
            CP_CG(dB + (uint32_t)(r * SSTRW + lcw) * 4, Bt + (size_t)(bn + r) * ldb + k0 + lcw * 2);
        }
        CP_COMMIT();
    };

    prefetch(0, 0);
    prefetch(1, 1);

    for (int it = 0; it < nk; it++) {
        if (it == nk - 1) { CP_WAIT(0); } else { CP_WAIT(1); }
        __syncthreads();

        uint32_t stA = sbase + (uint32_t)(it % 3) * STAGEW * 4;
        uint32_t stB = stA + ABUFW * 4;
        #pragma unroll
        for (int kk = 0; kk < 4; kk++) {
            uint32_t af[4][4], bf[4][2];
            #pragma unroll
            for (int mt = 0; mt < 4; mt++)
                ldsm4(af[mt][0], af[mt][1], af[mt][2], af[mt][3],
                      stA + aoff[mt] + kk * 32);
            ldsm4(bf[0][0], bf[0][1], bf[1][0], bf[1][1], stB + boff0 + kk * 32);
            ldsm4(bf[2][0], bf[2][1], bf[3][0], bf[3][1], stB + boff1 + kk * 32);
            #pragma unroll
            for (int mt = 0; mt < 4; mt++)
                #pragma unroll
                for (int nt = 0; nt < 4; nt++)
                    mma_f16(acc[mt][nt][0], acc[mt][nt][1],
                            acc[mt][nt][2], acc[mt][nt][3],
                            af[mt][0], af[mt][1], af[mt][2], af[mt][3],
                            bf[nt][0], bf[nt][1]);
        }
        if (it + 2 < nk) prefetch(it + 2, (it + 2) % 3);
    }

    #pragma unroll
    for (int mt = 0; mt < 4; mt++) {
        int r0 = bm + wm + mt * 16 + quad;
        #pragma unroll
        for (int nt = 0; nt < 4; nt++) {
            int c = bn + wn + nt * 8 + tig * 2;
            *reinterpret_cast<uint32_t*>(C + (size_t)r0 * ldc + c) =
                h2pack(acc[mt][nt][0], acc[mt][nt][1]);
            *reinterpret_cast<uint32_t*>(C + (size_t)(r0 + 8) * ldc + c) =
                h2pack(acc[mt][nt][2], acc[mt][nt][3]);
        }
    }
}

// ============================================================
// LayerNorm over DIM=1024, half output
// ============================================================
__global__ void ln_kernel(const float* __restrict__ x,
                          const float* __restrict__ g,
                          const float* __restrict__ b,
                          __half* __restrict__ out)
{
    int row = blockIdx.x;
    int tid = threadIdx.x;
    const float4 v = reinterpret_cast<const float4*>(x + (size_t)row * DIMC)[tid];

    float s  = v.x + v.y + v.z + v.w;
    float sq = v.x*v.x + v.y*v.y + v.z*v.z + v.w*v.w;
    #pragma unroll
    for (int o = 16; o > 0; o >>= 1) {
        s  += __shfl_xor_sync(0xffffffffu, s,  o);
        sq += __shfl_xor_sync(0xffffffffu, sq, o);
    }
    __shared__ float ws[8], wq[8];
    int warp = tid >> 5, lane = tid & 31;
    if (lane == 0) { ws[warp] = s; wq[warp] = sq; }
    __syncthreads();
    if (warp == 0) {
        float s2  = (lane < 8) ? ws[lane] : 0.f;
        float sq2 = (lane < 8) ? wq[lane] : 0.f;
        #pragma unroll
        for (int o = 4; o > 0; o >>= 1) {
            s2  += __shfl_xor_sync(0xffffffffu, s2,  o);
            sq2 += __shfl_xor_sync(0xffffffffu, sq2, o);
        }
        if (lane == 0) { ws[0] = s2; wq[0] = sq2; }
    }
    __syncthreads();
    float mean = ws[0] * (1.f / DIMC);
    float var  = wq[0] * (1.f / DIMC) - mean * mean;
    float rstd = rsqrtf(var + LN_EPS);

    float4 gg = reinterpret_cast<const float4*>(g)[tid];
    float4 bb = reinterpret_cast<const float4*>(b)[tid];
    uint2 o2;
    o2.x = h2pack((v.x - mean) * rstd * gg.x + bb.x,
                  (v.y - mean) * rstd * gg.y + bb.y);
    o2.y = h2pack((v.z - mean) * rstd * gg.z + bb.z,
                  (v.w - mean) * rstd * gg.w + bb.w);
    reinterpret_cast<uint2*>(out + (size_t)row * DIMC)[tid] = o2;
}

// ============================================================
// fp16 mma.sync GEMM, 3-stage cp.async pipeline, ldmatrix frags.
// mode 1: GEMM1-qkv — region 0 (qk): fused per-head LN (+log2 q scale)
//                     region 1: V->g_vt transposed
// mode 3: GEMM1-mlp slice: gelu epilogue, half out
// mode 2: C float + bias + resid (apply)    mode 0: plain half out
// ============================================================
__global__ void __launch_bounds__(256, 2)
mma_gemm(const __half* __restrict__ A, int lda,
         const __half* __restrict__ Bt, int ldb, int K1,
         const __half* __restrict__ A2, int lda2,
         const __half* __restrict__ Bt2, int ldb2, int K2,
         __half* __restrict__ Ch, int ldch,
         float* __restrict__ Cf, int ldcf,
         const float* __restrict__ bias, int nbias,
         const float* __restrict__ resid, int ldr,
         const float* __restrict__ qg, const float* __restrict__ qb,
         const float* __restrict__ kg, const float* __restrict__ kb,
         int mrow0, int mode)
{
    extern __shared__ uint32_t smw[];
    uint32_t sbase = smem_u32(smw);
    int tid  = threadIdx.x;
    int wid  = tid >> 5, lane = tid & 31;
    int quad = lane >> 2, tig = lane & 3;
    int bm = blockIdx.y * 128 + mrow0, bn = blockIdx.x * 128;
    int wm = (wid & 1) * 64, wn = (wid >> 1) * 32;

    float acc[4][4][4];
    #pragma unroll
    for (int i = 0; i < 4; i++)
        #pragma unroll
        for (int j = 0; j < 4; j++)
            #pragma unroll
            for (int r = 0; r < 4; r++) acc[i][j][r] = 0.f;

    int lr = tid >> 3;
    int lcw = (tid & 7) * 4;

    int lane15 = lane & 15;
    uint32_t aoff[4];
    #pragma unroll
    for (int mt = 0; mt < 4; mt++)
        aoff[mt] = (uint32_t)((wm + mt * 16 + lane15) * SSTRW) * 4 + (lane >> 4) * 16;
    uint32_t boff0 = (uint32_t)((wn + ((lane >> 4) << 3) + (lane & 7)) * SSTRW) * 4
                   + ((lane >> 3) & 1) * 16;
    uint32_t boff1 = boff0 + 16 * SSTRW * 4;

    const int nk1 = K1 >> 6;
    const int nk  = nk1 + (K2 >> 6);

    auto prefetch = [&](int it, int st) {
        const __half* Ab; const __half* Bb; int la, lb, k0;
        if (it < nk1) { Ab = A;  Bb = Bt;  la = lda;  lb = ldb;  k0 = it << 6; }
        else          { Ab = A2; Bb = Bt2; la = lda2; lb = ldb2; k0 = (it - nk1) << 6; }
        uint32_t dA = sbase + (uint32_t)st * STAGEW * 4;
        uint32_t dB = dA + ABUFW * 4;
        #pragma unroll
        for (int i = 0; i < 4; i++) {
            int r = i * 32 + lr;
            CP_CG(dA + (uint32_t)(r * SSTRW + lcw) * 4, Ab + (size_t)(bm + r) * la + k0 + lcw * 2);
            CP_CG(dB + (uint32_t)(r * SSTRW + lcw) * 4, Bb + (size_t)(bn + r) * lb + k0 + lcw * 2);
        }
        CP_COMMIT();
    };

    prefetch(0, 0);
    if (nk > 1) prefetch(1, 1);

    for (int it = 0; it < nk; it++) {
        if (it == nk - 1) { CP_WAIT(0); } else { CP_WAIT(1); }
        __syncthreads();

        uint32_t stA = sbase + (uint32_t)(it % 3) * STAGEW * 4;
        uint32_t stB = stA + ABUFW * 4;

        #pragma unroll
        for (int kk = 0; kk < 4; kk++) {
            uint32_t af[4][4], bf[4][2];
            #pragma unroll
            for (int mt = 0; mt < 4; mt++)
                ldsm4(af[mt][0], af[mt][1], af[mt][2], af[mt][3],
                      stA + aoff[mt] + kk * 32);
            ldsm4(bf[0][0], bf[0][1], bf[1][0], bf[1][1], stB + boff0 + kk * 32);
            ldsm4(bf[2][0], bf[2][1], bf[3][0], bf[3][1], stB + boff1 + kk * 32);
            #pragma unroll
            for (int mt = 0; mt < 4; mt++)
                #pragma unroll
                for (int nt = 0; nt < 4; nt++)
                    mma_f16(acc[mt][nt][0], acc[mt][nt][1],
                            acc[mt][nt][2], acc[mt][nt][3],
                            af[mt][0], af[mt][1], af[mt][2], af[mt][3],
                            bf[nt][0], bf[nt][1]);
        }
        if (it + 2 < nk) prefetch(it + 2, (it + 2) % 3);
    }

    int region = (mode != 1) ? -1 : ((bn < 2 * DIMC) ? 0 : 1);
    if (region == 0) __syncthreads();   // only QK-LN epilogue reuses smem

    if (region == 0) {
        float* ssum = reinterpret_cast<float*>(smw);       // [128][4]
        float* ssq  = ssum + 128 * 4;                      // [128][4]
        int ch = wn >> 5;

        #pragma unroll
        for (int mt = 0; mt < 4; mt++) {
            float slo = 0.f, sqlo = 0.f, shi = 0.f, sqhi = 0.f;
            #pragma unroll
            for (int nt = 0; nt < 4; nt++) {
                int c = bn + wn + nt * 8 + tig * 2;
                float b0 = bias[c], b1v = bias[c + 1];
                acc[mt][nt][0] += b0; acc[mt][nt][1] += b1v;
                acc[mt][nt][2] += b0; acc[mt][nt][3] += b1v;
                slo  += acc[mt][nt][0] + acc[mt][nt][1];
                sqlo += acc[mt][nt][0] * acc[mt][nt][0] + acc[mt][nt][1] * acc[mt][nt][1];
                shi  += acc[mt][nt][2] + acc[mt][nt][3];
                sqhi += acc[mt][nt][2] * acc[mt][nt][2] + acc[mt][nt][3] * acc[mt][nt][3];
            }
            slo  += __shfl_xor_sync(0xffffffffu, slo, 1);
            slo  += __shfl_xor_sync(0xffffffffu, slo, 2);
            sqlo += __shfl_xor_sync(0xffffffffu, sqlo, 1);
            sqlo += __shfl_xor_sync(0xffffffffu, sqlo, 2);
            shi  += __shfl_xor_sync(0xffffffffu, shi, 1);
            shi  += __shfl_xor_sync(0xffffffffu, shi, 2);
            sqhi += __shfl_xor_sync(0xffffffffu, sqhi, 1);
            sqhi += __shfl_xor_sync(0xffffffffu, sqhi, 2);
            if (tig == 0) {
                int rl = wm + mt * 16 + quad;
                ssum[rl * 4 + ch] = slo;        ssq[rl * 4 + ch] = sqlo;
                ssum[(rl + 8) * 4 + ch] = shi;  ssq[(rl + 8) * 4 + ch] = sqhi;
            }
        }
        __syncthreads();

        int hb = (wn >> 6) << 1;
        bool isq = (bn < DIMC);
        const float* gv = isq ? qg : kg;
        const float* bv = isq ? qb : kb;
        float qsc = isq ? QSCALE : 1.f;

        #pragma unroll
        for (int mt = 0; mt < 4; mt++) {
            int rl = wm + mt * 16 + quad;
            float mlo = (ssum[rl * 4 + hb] + ssum[rl * 4 + hb + 1]) * (1.f / 64.f);
            float vlo = (ssq[rl * 4 + hb] + ssq[rl * 4 + hb + 1]) * (1.f / 64.f) - mlo * mlo;
            float rlo = rsqrtf(vlo + LN_EPS);
            float mhi = (ssum[(rl + 8) * 4 + hb] + ssum[(rl + 8) * 4 + hb + 1]) * (1.f / 64.f);
            float vhi = (ssq[(rl + 8) * 4 + hb] + ssq[(rl + 8) * 4 + hb + 1]) * (1.f / 64.f) - mhi * mhi;
            float rhi = rsqrtf(vhi + LN_EPS);
            int r0 = bm + rl;
            #pragma unroll
            for (int nt = 0; nt < 4; nt++) {
                int c = bn + wn + nt * 8 + tig * 2;
                int d = c & 63;
                float g0 = gv[d], g1 = gv[d + 1];
                float e0 = bv[d], e1 = bv[d + 1];
                float o0 = ((acc[mt][nt][0] - mlo) * rlo * g0 + e0) * qsc;
                float o1 = ((acc[mt][nt][1] - mlo) * rlo * g1 + e1) * qsc;
                float o2 = ((acc[mt][nt][2] - mhi) * rhi * g0 + e0) * qsc;
                float o3 = ((acc[mt][nt][3] - mhi) * rhi * g1 + e1) * qsc;
                *reinterpret_cast<uint32_t*>(Ch + (size_t)r0 * ldch + c) = h2pack(o0, o1);
                *reinterpret_cast<uint32_t*>(Ch + (size_t)(r0 + 8) * ldch + c) = h2pack(o2, o3);
            }
        }
        return;
    }

    #pragma unroll
    for (int mt = 0; mt < 4; mt++) {
        int r0 = bm + wm + mt * 16 + quad;
        #pragma unroll
        for (int nt = 0; nt < 4; nt++) {
            int c = bn + wn + nt * 8 + tig * 2;
            float2 v0 = make_float2(acc[mt][nt][0], acc[mt][nt][1]);
            float2 v1 = make_float2(acc[mt][nt][2], acc[mt][nt][3]);
            if (bias) {
                float bx = (c     < nbias) ? bias[c]     : 0.f;
                float by = (c + 1 < nbias) ? bias[c + 1] : 0.f;
                v0.x += bx; v0.y += by;
                v1.x += bx; v1.y += by;
            }
            if (mode == 2) {
                float2 ra = *reinterpret_cast<const float2*>(resid + (size_t)r0 * ldr + c);
                float2 rb = *reinterpret_cast<const float2*>(resid + (size_t)(r0 + 8) * ldr + c);
                v0.x += ra.x; v0.y += ra.y;
                v1.x += rb.x; v1.y += rb.y;
                *reinterpret_cast<float2*>(Cf + (size_t)r0 * ldcf + c) = v0;
                *reinterpret_cast<float2*>(Cf + (size_t)(r0 + 8) * ldcf + c) = v1;
            } else if (region == 1) {
                int d = c - 2 * DIMC;
                int hh = d >> 6, dd = d & 63;
                int bbk = r0 >> 11, nn = r0 & 2047;
                size_t base = ((size_t)(bbk * NHEADS + hh) * DHEAD);
                g_vt[(base + dd    ) * NSEQ + nn    ] = __float2half(v0.x);
                g_vt[(base + dd + 1) * NSEQ + nn    ] = __float2half(v0.y);
                g_vt[(base + dd    ) * NSEQ + nn + 8] = __float2half(v1.x);
                g_vt[(base + dd + 1) * NSEQ + nn + 8] = __float2half(v1.y);
            } else {
                if (mode == 3) {
                    v0.x = gelu1(v0.x); v0.y = gelu1(v0.y);
                    v1.x = gelu1(v1.x); v1.y = gelu1(v1.y);
                }
                *reinterpret_cast<uint32_t*>(Ch + (size_t)r0 * ldch + c) = h2pack(v0.x, v0.y);
                *reinterpret_cast<uint32_t*>(Ch + (size_t)(r0 + 8) * ldch + c) = h2pack(v1.x, v1.y);
            }
        }
    }
}

// ============================================================
// Flash attention: fp16 m16n8k16, no online max (LN-bounded scores),
// p = 2^s via ex2.approx.f16x2, l via ones-MMA. TRIPLE-buffered K/V:
// prefetch distance 1 => buffer written at iter t was last read at
// iter t-2, so a CTA barrier every OTHER tile suffices (16 vs 32).
// ============================================================
#define KSTRW 36
#define QWORDS (128 * KSTRW)
#define KVWORDS (64 * KSTRW)
#define ATTN_SMEM ((QWORDS + 6 * KVWORDS) * 4)   // 73728 B
#define ONESF  0x3C003C00u
#define CLAMP2 0x4BC04BC0u   // half2(15.5); score bound is ~13.3

__global__ void __launch_bounds__(256, 2)
fattn_kernel(const __half* __restrict__ fused, __half* __restrict__ aout, int bbase)
{
    extern __shared__ uint32_t smw[];
    uint32_t sbase = smem_u32(smw);

    int tid  = threadIdx.x;
    int wid  = tid >> 5, lane = tid & 31;
    int quad = lane >> 2, tig = lane & 3;
    int lane15 = lane & 15;
    int h  = blockIdx.y;
    int bb = blockIdx.z + bbase;
    int q0 = blockIdx.x * 128;
    int tq0 = bb * NSEQ + q0;
    int kvb = bb * NSEQ;
    const __half* vtb = g_vt + (size_t)(bb * NHEADS + h) * DHEAD * NSEQ;

    auto prefetch_kv = [&](int kt, int buf) {
        uint32_t dK = sbase + (uint32_t)(QWORDS + buf * 2 * KVWORDS) * 4;
        uint32_t dV = dK + KVWORDS * 4;
        #pragma unroll
        for (int i = 0; i < 2; i++) {
            int idx = i * 256 + tid;
            int r = idx >> 3, chh = (idx & 7) * 8;
            CP_CG(dK + (uint32_t)(r * KSTRW + chh / 2) * 4,
                  fused + (size_t)(kvb + kt + r) * FWP + DIMC + h * DHEAD + chh);
            CP_CG(dV + (uint32_t)(r * KSTRW + chh / 2) * 4,
                  vtb + (size_t)r * NSEQ + kt + chh);
        }
        CP_COMMIT();
    };

    #pragma unroll
    for (int i = 0; i < 4; i++) {
        int idx = i * 256 + tid;
        int r = idx >> 3, chh = (idx & 7) * 8;
        CP_CA(sbase + (uint32_t)(r * KSTRW + chh / 2) * 4,
              fused + (size_t)(tq0 + r) * FWP + h * DHEAD + chh);
    }
    prefetch_kv(0, 0);
    CP_WAIT(0);
    __syncthreads();

    uint32_t aPat = (uint32_t)(lane15 * KSTRW) * 4 + (lane >> 4) * 16;
    uint32_t bPat = (uint32_t)((((lane >> 4) << 3) + (lane & 7)) * KSTRW) * 4
                  + ((lane >> 3) & 1) * 16;
    uint32_t sPat = (uint32_t)(((((lane >> 3) & 1) << 3) + (lane & 7)) * KSTRW) * 4
                  + (lane >> 4) * 16;

    uint32_t qf[4][4];
    {
        uint32_t qbase = sbase + (uint32_t)(wid * 16 * KSTRW) * 4 + aPat;
        #pragma unroll
        for (int kc = 0; kc < 4; kc++)
            ldsm4(qf[kc][0], qf[kc][1], qf[kc][2], qf[kc][3], qbase + kc * 32);
    }
    uint32_t pBase = sbase + (uint32_t)(wid * 16 * KSTRW) * 4;

    float o[8][4];
    #pragma unroll
    for (int i = 0; i < 8; i++)
        #pragma unroll
        for (int j = 0; j < 4; j++) o[i][j] = 0.f;
    float ls[4] = {0.f, 0.f, 0.f, 0.f};

    const int NT = NSEQ / 64;   // 32 tiles
    for (int t = 0; t < NT; t++) {
        int b = t % 3;
        if (t + 1 < NT) prefetch_kv((t + 1) * 64, (t + 1) % 3);

        uint32_t kBase = sbase + (uint32_t)(QWORDS + b * 2 * KVWORDS) * 4;
        uint32_t vBase = kBase + KVWORDS * 4;

        float sc[8][4];
        #pragma unroll
        for (int i = 0; i < 8; i++)
            #pragma unroll
            for (int j = 0; j < 4; j++) sc[i][j] = 0.f;

        #pragma unroll
        for (int kc = 0; kc < 4; kc++) {
            #pragma unroll
            for (int np = 0; np < 4; np++) {
                uint32_t b00, b01, b10, b11;
                ldsm4(b00, b01, b10, b11,
                      kBase + (uint32_t)(np * 16 * KSTRW) * 4 + bPat + kc * 32);
                mma_f16(sc[2*np][0], sc[2*np][1], sc[2*np][2], sc[2*np][3],
                        qf[kc][0], qf[kc][1], qf[kc][2], qf[kc][3], b00, b01);
                mma_f16(sc[2*np+1][0], sc[2*np+1][1], sc[2*np+1][2], sc[2*np+1][3],
                        qf[kc][0], qf[kc][1], qf[kc][2], qf[kc][3], b10, b11);
            }
        }

        uint32_t hl0[8], hl1[8];
        #pragma unroll
        for (int nf = 0; nf < 8; nf++) {
            hl0[nf] = h2exp2(h2minc(h2pack(sc[nf][0], sc[nf][1]), CLAMP2));
            hl1[nf] = h2exp2(h2minc(h2pack(sc[nf][2], sc[nf][3]), CLAMP2));
        }
        #pragma unroll
        for (int np = 0; np < 4; np++)
            stsm4(pBase + sPat + np * 32,
                  hl0[2*np], hl1[2*np], hl0[2*np+1], hl1[2*np+1]);
        __syncwarp();

        #pragma unroll
        for (int kc = 0; kc < 4; kc++) {
            uint32_t a0, a1, a2, a3;
            ldsm4(a0, a1, a2, a3, pBase + aPat + kc * 32);
            mma_f16(ls[0], ls[1], ls[2], ls[3], a0, a1, a2, a3, ONESF, ONESF);
            #pragma unroll
            for (int np = 0; np < 4; np++) {
                uint32_t b00, b01, b10, b11;
                ldsm4(b00, b01, b10, b11,
                      vBase + (uint32_t)(np * 16 * KSTRW) * 4 + bPat + kc * 32);
                mma_f16(o[2*np][0], o[2*np][1], o[2*np][2], o[2*np][3],
                        a0, a1, a2, a3, b00, b01);
                mma_f16(o[2*np+1][0], o[2*np+1][1], o[2*np+1][2], o[2*np+1][3],
                        a0, a1, a2, a3, b10, b11);
            }
        }
        __syncwarp();

        if (t + 1 < NT) { CP_WAIT(0); }
        if ((t & 1) && (t + 1 < NT)) __syncthreads();   // barrier every other tile
    }

    float il0 = 1.f / ls[0], il1 = 1.f / ls[2];
    int r0 = tq0 + wid * 16 + quad;
    #pragma unroll
    for (int nf = 0; nf < 8; nf++) {
        int c = h * DHEAD + nf * 8 + tig * 2;
        *reinterpret_cast<uint32_t*>(aout + (size_t)r0 * DIMC + c) =
            h2pack(o[nf][0] * il0, o[nf][1] * il0);
        *reinterpret_cast<uint32_t*>(aout + (size_t)(r0 + 8) * DIMC + c) =
            h2pack(o[nf][2] * il1, o[nf][3] * il1);
    }
}

// ============================================================
// launch — exact R12 schedule (verified best)
// ============================================================
extern "C" void kernel_launch(void* const* d_in, const int* in_sizes, int n_in,
                              void* d_out, int out_size)
{
    const float* x      = (const float*)d_in[0];
    const float* norm_g = (const float*)d_in[1];
    const float* norm_b = (const float*)d_in[2];
    const float* W1     = (const float*)d_in[3];
    const float* b1     = (const float*)d_in[4];
    const float* qn_g   = (const float*)d_in[5];
    const float* qn_b   = (const float*)d_in[6];
    const float* kn_g   = (const float*)d_in[7];
    const float* kn_b   = (const float*)d_in[8];
    const float* Wao    = (const float*)d_in[9];
    const float* bao    = (const float*)d_in[10];
    const float* Wmo    = (const float*)d_in[11];
    const float* bmo    = (const float*)d_in[12];
    const float* W2     = (const float*)d_in[13];
    const float* b2     = (const float*)d_in[14];
    float*       out    = (float*)d_out;

    __half *norm, *fused, *attn, *w1t, *wfa, *wfm;
    float *beff;
    cudaGetSymbolAddress((void**)&norm,  g_norm);
    cudaGetSymbolAddress((void**)&fused, g_fused);
    cudaGetSymbolAddress((void**)&attn,  g_attn);
    cudaGetSymbolAddress((void**)&w1t,   g_w1t);
    cudaGetSymbolAddress((void**)&wfa,   g_wfa);
    cudaGetSymbolAddress((void**)&wfm,   g_wfm);
    cudaGetSymbolAddress((void**)&beff,  g_beff);

    static bool inited = false;
    static cudaStream_t s2;
    static cudaEvent_t ev1, evw1, evg1, ev3;
    if (!inited) {
        cudaStreamCreateWithFlags(&s2, cudaStreamNonBlocking);
        cudaEventCreateWithFlags(&ev1, cudaEventDisableTiming);
        cudaEventCreateWithFlags(&evw1, cudaEventDisableTiming);
        cudaEventCreateWithFlags(&evg1, cudaEventDisableTiming);
        cudaEventCreateWithFlags(&ev3, cudaEventDisableTiming);
        cudaFuncSetAttribute(mma_gemm, cudaFuncAttributeMaxDynamicSharedMemorySize, GEMM_SMEM);
        cudaFuncSetAttribute(fold_kernel, cudaFuncAttributeMaxDynamicSharedMemorySize, GEMM_SMEM);
        cudaFuncSetAttribute(fattn_kernel, cudaFuncAttributeMaxDynamicSharedMemorySize, ATTN_SMEM);
        inited = true;
    }

    // ---- fork: side chain (prep_w1 -> prep_rest -> fold), later the mlp slice
    cudaEventRecord(ev1, 0);
    cudaStreamWaitEvent(s2, ev1, 0);
    prep_w1_kernel<<<3840, 256, 0, s2>>>(W1);
    cudaEventRecord(evw1, s2);
    prep_rest_kernel<<<9280, 256, 0, s2>>>(W2, Wao, Wmo, bao, bmo, b2);
    fold_kernel<<<116, 256, GEMM_SMEM, s2>>>();

    // ---- main chain: ln concurrent with prep_w1
    ln_kernel<<<NTOK, 256>>>(x, norm_g, norm_b, norm);
    cudaStreamWaitEvent(0, evw1, 0);

    // GEMM1-qkv (cols 0..3071): qk->LN'd fused, V->g_vt transposed
    mma_gemm<<<dim3(24, NTOK / 128), 256, GEMM_SMEM>>>(
        norm, DIMC, w1t, DIMC, DIMC,
        nullptr, 0, nullptr, 0, 0,
        fused, FWP, nullptr, 0, b1, FW, nullptr, 0,
        qn_g, qn_b, kn_g, kn_b, 0, 1);
    cudaEventRecord(evg1, 0);

    // side stream: GEMM1-mlp slice (cols 3072.., gelu) overlaps fattn
    cudaStreamWaitEvent(s2, evg1, 0);
    mma_gemm<<<dim3(6, NTOK / 128), 256, GEMM_SMEM, s2>>>(
        norm, DIMC, w1t + (size_t)(3 * DIMC) * DIMC, DIMC, DIMC,
        nullptr, 0, nullptr, 0, 0,
        fused + 3 * DIMC, FWP, nullptr, 0, b1 + 3 * DIMC, FW - 3 * DIMC, nullptr, 0,
        nullptr, nullptr, nullptr, nullptr, 0, 3);
    cudaEventRecord(ev3, s2);

    // flash attention (monolithic, main stream)
    fattn_kernel<<<dim3(NSEQ / 128, NHEADS, 2), 256, ATTN_SMEM>>>(fused, attn, 0);

    // ---- join, then apply: out = x + attn @ wfa^T + gelu_hidden @ wfm^T + beff
    cudaStreamWaitEvent(0, ev3, 0);
    mma_gemm<<<dim3(DIMC / 128, NTOK / 128), 256, GEMM_SMEM>>>(
        attn, DIMC, wfa, DIMC, DIMC,
        fused + 3 * DIMC, FWP, wfm, HIDPAD, HIDPAD,
        nullptr, 0, out, DIMC, beff, DIMC, x, DIMC,
        nullptr, nullptr, nullptr, nullptr, 0, 2);
}

// round 16
// speedup vs baseline: 1.6107x; 1.0312x over previous
#include <cuda_runtime.h>
#include <cuda_fp16.h>
#include <math.h>
#include <stdint.h>

// ---------------- problem constants ----------------
#define NTOK   4096              // B*N = 2*2048
#define DIMC   1024
#define NHEADS 16
#define DHEAD  64
#define MLPHID 716
#define FW     3788              // 3*DIM + MLP_HID (true width)
#define FWP    3840              // padded to 30*128
#define HIDPAD 768               // Wmo rows padded; K2 of apply
#define NSEQ   2048
#define LN_EPS 1e-6f
#define NSLICE 16
#define QSCALE 0.1803368801111204f   // 0.125 * log2(e): softmax in 2^s domain

// ---------------- scratch (static device globals) ------
__device__ __half g_norm [NTOK * DIMC];
__device__ __half g_fused[NTOK * FWP];
__device__ __half g_vt   [2 * NHEADS * DHEAD * NSEQ];   // V transposed [b][h][d][n]
__device__ __half g_attn [NTOK * DIMC];
__device__ __half g_w1t  [FWP  * DIMC];
__device__ __half g_w2t  [DIMC * 2 * DIMC];
__device__ __half g_waor [DIMC * DIMC];
__device__ __half g_wmor [HIDPAD * DIMC];
__device__ __half g_wfa  [DIMC * DIMC];
__device__ __half g_wfm  [DIMC * HIDPAD];
__device__ float  g_beff [DIMC];
__device__ float  g_beffp[NSLICE * DIMC];

// ================= helpers =================
__device__ __forceinline__ uint32_t smem_u32(const void* p) {
    uint32_t a;
    asm("{ .reg .u64 t; cvta.to.shared.u64 t, %1; cvt.u32.u64 %0, t; }" : "=r"(a) : "l"(p));
    return a;
}
__device__ __forceinline__ void mma_f16(float& d0, float& d1, float& d2, float& d3,
                                        uint32_t a0, uint32_t a1, uint32_t a2, uint32_t a3,
                                        uint32_t b0, uint32_t b1)
{
    asm volatile(
        "mma.sync.aligned.m16n8k16.row.col.f32.f16.f16.f32 "
        "{%0,%1,%2,%3}, {%4,%5,%6,%7}, {%8,%9}, {%0,%1,%2,%3};"
        : "+f"(d0), "+f"(d1), "+f"(d2), "+f"(d3)
        : "r"(a0), "r"(a1), "r"(a2), "r"(a3), "r"(b0), "r"(b1));
}
__device__ __forceinline__ void ldsm4(uint32_t& r0, uint32_t& r1, uint32_t& r2, uint32_t& r3,
                                      uint32_t addr)
{
    asm volatile("ldmatrix.sync.aligned.m8n8.x4.shared.b16 {%0,%1,%2,%3}, [%4];"
                 : "=r"(r0), "=r"(r1), "=r"(r2), "=r"(r3) : "r"(addr));
}
__device__ __forceinline__ void stsm4(uint32_t addr, uint32_t r0, uint32_t r1,
                                      uint32_t r2, uint32_t r3)
{
    asm volatile("stmatrix.sync.aligned.m8n8.x4.shared.b16 [%0], {%1,%2,%3,%4};"
                 :: "r"(addr), "r"(r0), "r"(r1), "r"(r2), "r"(r3) : "memory");
}
__device__ __forceinline__ float gelu1(float x) {
    float u = 0.7978845608028654f * (x + 0.044715f * x * x * x);
    return 0.5f * x * (1.f + tanhf(u));
}
__device__ __forceinline__ uint32_t h2pack(float a, float b) {
    __half2 h = __floats2half2_rn(a, b);
    return *reinterpret_cast<uint32_t*>(&h);
}
__device__ __forceinline__ uint32_t h2exp2(uint32_t v) {
    uint32_t r; asm("ex2.approx.f16x2 %0, %1;" : "=r"(r) : "r"(v)); return r;
}
__device__ __forceinline__ uint32_t h2minc(uint32_t v, uint32_t c) {
    __half2 a = *reinterpret_cast<__half2*>(&v);
    __half2 b = *reinterpret_cast<__half2*>(&c);
    __half2 m = __hmin2(a, b);
    return *reinterpret_cast<uint32_t*>(&m);
}
#define CP_CA(dst, src) asm volatile("cp.async.ca.shared.global [%0], [%1], 16;" :: "r"(dst), "l"(src) : "memory")
#define CP_CG(dst, src) asm volatile("cp.async.cg.shared.global [%0], [%1], 16;" :: "r"(dst), "l"(src) : "memory")
#define CP_COMMIT()     asm volatile("cp.async.commit_group;" ::: "memory")
#define CP_WAIT(n)      asm volatile("cp.async.wait_group %0;" :: "n"(n) : "memory")

// ============================================================
// prep_w1: W1 [1024 x 3788] -> w1t [3840][1024] (half), 3840 blocks
// ============================================================
__global__ void prep_w1_kernel(const float* __restrict__ W1)
{
    __shared__ float t[32][33];
    int bid = blockIdx.x, tid = threadIdx.x;
    int tx = tid & 31, ty = tid >> 5;
    int bx = bid % (FWP / 32), by = bid / (FWP / 32);
    int n0 = bx * 32, k0 = by * 32;
    #pragma unroll
    for (int i = 0; i < 32; i += 8) {
        int n = n0 + tx;
        t[ty + i][tx] = (n < FW) ? W1[(size_t)(k0 + ty + i) * FW + n] : 0.f;
    }
    __syncthreads();
    #pragma unroll
    for (int i = 0; i < 32; i += 8)
        g_w1t[(size_t)(n0 + ty + i) * DIMC + k0 + tx] = __float2half(t[tx][ty + i]);
}

// ============================================================
// prep_rest: W2^T, Wao copy, Wmo copy(pad), beff partials — 9280 blocks
// ============================================================
__global__ void prep_rest_kernel(const float* __restrict__ W2,
                                 const float* __restrict__ Wao,
                                 const float* __restrict__ Wmo,
                                 const float* __restrict__ bao,
                                 const float* __restrict__ bmo,
                                 const float* __restrict__ b2)
{
    __shared__ float t[32][33];
    int bid = blockIdx.x, tid = threadIdx.x;
    int tx = tid & 31, ty = tid >> 5;

    if (bid < 2048) {
        int bx = bid % 32, by = bid / 32;
        int n0 = bx * 32, k0 = by * 32;
        #pragma unroll
        for (int i = 0; i < 32; i += 8)
            t[ty + i][tx] = W2[(size_t)(k0 + ty + i) * DIMC + n0 + tx];
        __syncthreads();
        #pragma unroll
        for (int i = 0; i < 32; i += 8)
            g_w2t[(size_t)(n0 + ty + i) * 2 * DIMC + k0 + tx] = __float2half(t[tx][ty + i]);
    } else if (bid < 6144) {
        int idx = (bid - 2048) * 256 + tid;
        g_waor[idx] = __float2half(Wao[idx]);
    } else if (bid < 9216) {
        int idx = (bid - 6144) * 256 + tid;
        int r = idx >> 10, c = idx & 1023;
        g_wmor[idx] = (r < MLPHID) ? __float2half(Wmo[(size_t)r * DIMC + c])
                                   : __float2half(0.f);
    } else {
        int b = bid - 9216;
        int n = (b & 3) * 256 + tid;
        int s = b >> 2;
        float acc = (s == 0) ? b2[n] : 0.f;
        int k0 = s * (2048 / NSLICE), k1 = k0 + (2048 / NSLICE);
        for (int k = k0; k < k1; k++) {
            float c = (k < 1024) ? bao[k] : bmo[k - 1024];
            acc += c * W2[(size_t)k * DIMC + n];
        }
        g_beffp[s * DIMC + n] = acc;
    }
}

// ============================================================
// merged fold launch: BOTH weight folds + beff reduce, one wave.
// ============================================================
#define SSTRW 36
#define ABUFW (128 * SSTRW)
#define STAGEW (2 * ABUFW)
#define GEMM_SMEM (3 * STAGEW * 4)   // 110592 B

__global__ void __launch_bounds__(256, 2)
fold_kernel()
{
    extern __shared__ uint32_t smw[];
    int bid = blockIdx.x, tid = threadIdx.x;

    if (bid >= 112) {
        int n = (bid - 112) * 256 + tid;
        float s = 0.f;
        #pragma unroll
        for (int i = 0; i < NSLICE; i++) s += g_beffp[i * DIMC + n];
        g_beff[n] = s;
        return;
    }

    const __half* A; const __half* Bt; __half* C;
    int lda, ldb, ldc, bm, bn;
    if (bid < 64) {
        A = g_w2t;  lda = 2 * DIMC; Bt = g_waor; ldb = DIMC;
        C = g_wfa;  ldc = DIMC;
        bn = (bid & 7) * 128; bm = (bid >> 3) * 128;
    } else {
        int b = bid - 64;
        A = g_w2t + DIMC; lda = 2 * DIMC; Bt = g_wmor; ldb = DIMC;
        C = g_wfm; ldc = HIDPAD;
        bn = (b % 6) * 128; bm = (b / 6) * 128;
    }

    uint32_t sbase = smem_u32(smw);
    int wid = tid >> 5, lane = tid & 31;
    int quad = lane >> 2, tig = lane & 3;
    int wm = (wid & 1) * 64, wn = (wid >> 1) * 32;
    int lr = tid >> 3, lcw = (tid & 7) * 4;
    int lane15 = lane & 15;

    float acc[4][4][4];
    #pragma unroll
    for (int i = 0; i < 4; i++)
        #pragma unroll
        for (int j = 0; j < 4; j++)
            #pragma unroll
            for (int r = 0; r < 4; r++) acc[i][j][r] = 0.f;

    uint32_t aoff[4];
    #pragma unroll
    for (int mt = 0; mt < 4; mt++)
        aoff[mt] = (uint32_t)((wm + mt * 16 + lane15) * SSTRW) * 4 + (lane >> 4) * 16;
    uint32_t boff0 = (uint32_t)((wn + ((lane >> 4) << 3) + (lane & 7)) * SSTRW) * 4
                   + ((lane >> 3) & 1) * 16;
    uint32_t boff1 = boff0 + 16 * SSTRW * 4;

    const int nk = DIMC >> 6;     // 16

    auto prefetch = [&](int it, int st) {
        int k0 = it << 6;
        uint32_t dA = sbase + (uint32_t)st * STAGEW * 4;
        uint32_t dB = dA + ABUFW * 4;
        #pragma unroll
        for (int i = 0; i < 4; i++) {
            int r = i * 32 + lr;
            CP_CG(dA + (uint32_t)(r * SSTRW + lcw) * 4, A + (size_t)(bm + r) * lda + k0 + lcw * 2);
            CP_CG(dB + (uint32_t)(r * SSTRW + lcw) * 4, Bt + (size_t)(bn + r) * ldb + k0 + lcw * 2);
        }
        CP_COMMIT();
    };

    prefetch(0, 0);
    prefetch(1, 1);

    for (int it = 0; it < nk; it++) {
        if (it == nk - 1) { CP_WAIT(0); } else { CP_WAIT(1); }
        __syncthreads();

        uint32_t stA = sbase + (uint32_t)(it % 3) * STAGEW * 4;
        uint32_t stB = stA + ABUFW * 4;
        #pragma unroll
        for (int kk = 0; kk < 4; kk++) {
            uint32_t af[4][4], bf[4][2];
            #pragma unroll
            for (int mt = 0; mt < 4; mt++)
                ldsm4(af[mt][0], af[mt][1], af[mt][2], af[mt][3],
                      stA + aoff[mt] + kk * 32);
            ldsm4(bf[0][0], bf[0][1], bf[1][0], bf[1][1], stB + boff0 + kk * 32);
            ldsm4(bf[2][0], bf[2][1], bf[3][0], bf[3][1], stB + boff1 + kk * 32);
            #pragma unroll
            for (int mt = 0; mt < 4; mt++)
                #pragma unroll
                for (int nt = 0; nt < 4; nt++)
                    mma_f16(acc[mt][nt][0], acc[mt][nt][1],
                            acc[mt][nt][2], acc[mt][nt][3],
                            af[mt][0], af[mt][1], af[mt][2], af[mt][3],
                            bf[nt][0], bf[nt][1]);
        }
        if (it + 2 < nk) prefetch(it + 2, (it + 2) % 3);
    }

    #pragma unroll
    for (int mt = 0; mt < 4; mt++) {
        int r0 = bm + wm + mt * 16 + quad;
        #pragma unroll
        for (int nt = 0; nt < 4; nt++) {
            int c = bn + wn + nt * 8 + tig * 2;
            *reinterpret_cast<uint32_t*>(C + (size_t)r0 * ldc + c) =
                h2pack(acc[mt][nt][0], acc[mt][nt][1]);
            *reinterpret_cast<uint32_t*>(C + (size_t)(r0 + 8) * ldc + c) =
                h2pack(acc[mt][nt][2], acc[mt][nt][3]);
        }
    }
}

// ============================================================
// LayerNorm over DIM=1024, half output
// ============================================================
__global__ void ln_kernel(const float* __restrict__ x,
                          const float* __restrict__ g,
                          const float* __restrict__ b,
                          __half* __restrict__ out)
{
    int row = blockIdx.x;
    int tid = threadIdx.x;
    const float4 v = reinterpret_cast<const float4*>(x + (size_t)row * DIMC)[tid];

    float s  = v.x + v.y + v.z + v.w;
    float sq = v.x*v.x + v.y*v.y + v.z*v.z + v.w*v.w;
    #pragma unroll
    for (int o = 16; o > 0; o >>= 1) {
        s  += __shfl_xor_sync(0xffffffffu, s,  o);
        sq += __shfl_xor_sync(0xffffffffu, sq, o);
    }
    __shared__ float ws[8], wq[8];
    int warp = tid >> 5, lane = tid & 31;
    if (lane == 0) { ws[warp] = s; wq[warp] = sq; }
    __syncthreads();
    if (warp == 0) {
        float s2  = (lane < 8) ? ws[lane] : 0.f;
        float sq2 = (lane < 8) ? wq[lane] : 0.f;
        #pragma unroll
        for (int o = 4; o > 0; o >>= 1) {
            s2  += __shfl_xor_sync(0xffffffffu, s2,  o);
            sq2 += __shfl_xor_sync(0xffffffffu, sq2, o);
        }
        if (lane == 0) { ws[0] = s2; wq[0] = sq2; }
    }
    __syncthreads();
    float mean = ws[0] * (1.f / DIMC);
    float var  = wq[0] * (1.f / DIMC) - mean * mean;
    float rstd = rsqrtf(var + LN_EPS);

    float4 gg = reinterpret_cast<const float4*>(g)[tid];
    float4 bb = reinterpret_cast<const float4*>(b)[tid];
    uint2 o2;
    o2.x = h2pack((v.x - mean) * rstd * gg.x + bb.x,
                  (v.y - mean) * rstd * gg.y + bb.y);
    o2.y = h2pack((v.z - mean) * rstd * gg.z + bb.z,
                  (v.w - mean) * rstd * gg.w + bb.w);
    reinterpret_cast<uint2*>(out + (size_t)row * DIMC)[tid] = o2;
}

// ============================================================
// fp16 mma.sync GEMM, 3-stage cp.async pipeline, ldmatrix frags.
// mode 1: GEMM1-qkv — region 0 (qk): fused per-head LN (+log2 q scale)
//                     region 1: V->g_vt transposed
// mode 3: GEMM1-mlp slice: gelu epilogue, half out
// mode 2: C float + bias + resid (apply)    mode 0: plain half out
// ============================================================
__global__ void __launch_bounds__(256, 2)
mma_gemm(const __half* __restrict__ A, int lda,
         const __half* __restrict__ Bt, int ldb, int K1,
         const __half* __restrict__ A2, int lda2,
         const __half* __restrict__ Bt2, int ldb2, int K2,
         __half* __restrict__ Ch, int ldch,
         float* __restrict__ Cf, int ldcf,
         const float* __restrict__ bias, int nbias,
         const float* __restrict__ resid, int ldr,
         const float* __restrict__ qg, const float* __restrict__ qb,
         const float* __restrict__ kg, const float* __restrict__ kb,
         int mrow0, int mode)
{
    extern __shared__ uint32_t smw[];
    uint32_t sbase = smem_u32(smw);
    int tid  = threadIdx.x;
    int wid  = tid >> 5, lane = tid & 31;
    int quad = lane >> 2, tig = lane & 3;
    int bm = blockIdx.y * 128 + mrow0, bn = blockIdx.x * 128;
    int wm = (wid & 1) * 64, wn = (wid >> 1) * 32;

    float acc[4][4][4];
    #pragma unroll
    for (int i = 0; i < 4; i++)
        #pragma unroll
        for (int j = 0; j < 4; j++)
            #pragma unroll
            for (int r = 0; r < 4; r++) acc[i][j][r] = 0.f;

    int lr = tid >> 3;
    int lcw = (tid & 7) * 4;

    int lane15 = lane & 15;
    uint32_t aoff[4];
    #pragma unroll
    for (int mt = 0; mt < 4; mt++)
        aoff[mt] = (uint32_t)((wm + mt * 16 + lane15) * SSTRW) * 4 + (lane >> 4) * 16;
    uint32_t boff0 = (uint32_t)((wn + ((lane >> 4) << 3) + (lane & 7)) * SSTRW) * 4
                   + ((lane >> 3) & 1) * 16;
    uint32_t boff1 = boff0 + 16 * SSTRW * 4;

    const int nk1 = K1 >> 6;
    const int nk  = nk1 + (K2 >> 6);

    auto prefetch = [&](int it, int st) {
        const __half* Ab; const __half* Bb; int la, lb, k0;
        if (it < nk1) { Ab = A;  Bb = Bt;  la = lda;  lb = ldb;  k0 = it << 6; }
        else          { Ab = A2; Bb = Bt2; la = lda2; lb = ldb2; k0 = (it - nk1) << 6; }
        uint32_t dA = sbase + (uint32_t)st * STAGEW * 4;
        uint32_t dB = dA + ABUFW * 4;
        #pragma unroll
        for (int i = 0; i < 4; i++) {
            int r = i * 32 + lr;
            CP_CG(dA + (uint32_t)(r * SSTRW + lcw) * 4, Ab + (size_t)(bm + r) * la + k0 + lcw * 2);
            CP_CG(dB + (uint32_t)(r * SSTRW + lcw) * 4, Bb + (size_t)(bn + r) * lb + k0 + lcw * 2);
        }
        CP_COMMIT();
    };

    prefetch(0, 0);
    if (nk > 1) prefetch(1, 1);

    for (int it = 0; it < nk; it++) {
        if (it == nk - 1) { CP_WAIT(0); } else { CP_WAIT(1); }
        __syncthreads();

        uint32_t stA = sbase + (uint32_t)(it % 3) * STAGEW * 4;
        uint32_t stB = stA + ABUFW * 4;

        #pragma unroll
        for (int kk = 0; kk < 4; kk++) {
            uint32_t af[4][4], bf[4][2];
            #pragma unroll
            for (int mt = 0; mt < 4; mt++)
                ldsm4(af[mt][0], af[mt][1], af[mt][2], af[mt][3],
                      stA + aoff[mt] + kk * 32);
            ldsm4(bf[0][0], bf[0][1], bf[1][0], bf[1][1], stB + boff0 + kk * 32);
            ldsm4(bf[2][0], bf[2][1], bf[3][0], bf[3][1], stB + boff1 + kk * 32);
            #pragma unroll
            for (int mt = 0; mt < 4; mt++)
                #pragma unroll
                for (int nt = 0; nt < 4; nt++)
                    mma_f16(acc[mt][nt][0], acc[mt][nt][1],
                            acc[mt][nt][2], acc[mt][nt][3],
                            af[mt][0], af[mt][1], af[mt][2], af[mt][3],
                            bf[nt][0], bf[nt][1]);
        }
        if (it + 2 < nk) prefetch(it + 2, (it + 2) % 3);
    }

    int region = (mode != 1) ? -1 : ((bn < 2 * DIMC) ? 0 : 1);
    if (region == 0) __syncthreads();   // only QK-LN epilogue reuses smem

    if (region == 0) {
        float* ssum = reinterpret_cast<float*>(smw);       // [128][4]
        float* ssq  = ssum + 128 * 4;                      // [128][4]
        int ch = wn >> 5;

        #pragma unroll
        for (int mt = 0; mt < 4; mt++) {
            float slo = 0.f, sqlo = 0.f, shi = 0.f, sqhi = 0.f;
            #pragma unroll
            for (int nt = 0; nt < 4; nt++) {
                int c = bn + wn + nt * 8 + tig * 2;
                float b0 = bias[c], b1v = bias[c + 1];
                acc[mt][nt][0] += b0; acc[mt][nt][1] += b1v;
                acc[mt][nt][2] += b0; acc[mt][nt][3] += b1v;
                slo  += acc[mt][nt][0] + acc[mt][nt][1];
                sqlo += acc[mt][nt][0] * acc[mt][nt][0] + acc[mt][nt][1] * acc[mt][nt][1];
                shi  += acc[mt][nt][2] + acc[mt][nt][3];
                sqhi += acc[mt][nt][2] * acc[mt][nt][2] + acc[mt][nt][3] * acc[mt][nt][3];
            }
            slo  += __shfl_xor_sync(0xffffffffu, slo, 1);
            slo  += __shfl_xor_sync(0xffffffffu, slo, 2);
            sqlo += __shfl_xor_sync(0xffffffffu, sqlo, 1);
            sqlo += __shfl_xor_sync(0xffffffffu, sqlo, 2);
            shi  += __shfl_xor_sync(0xffffffffu, shi, 1);
            shi  += __shfl_xor_sync(0xffffffffu, shi, 2);
            sqhi += __shfl_xor_sync(0xffffffffu, sqhi, 1);
            sqhi += __shfl_xor_sync(0xffffffffu, sqhi, 2);
            if (tig == 0) {
                int rl = wm + mt * 16 + quad;
                ssum[rl * 4 + ch] = slo;        ssq[rl * 4 + ch] = sqlo;
                ssum[(rl + 8) * 4 + ch] = shi;  ssq[(rl + 8) * 4 + ch] = sqhi;
            }
        }
        __syncthreads();

        int hb = (wn >> 6) << 1;
        bool isq = (bn < DIMC);
        const float* gv = isq ? qg : kg;
        const float* bv = isq ? qb : kb;
        float qsc = isq ? QSCALE : 1.f;

        #pragma unroll
        for (int mt = 0; mt < 4; mt++) {
            int rl = wm + mt * 16 + quad;
            float mlo = (ssum[rl * 4 + hb] + ssum[rl * 4 + hb + 1]) * (1.f / 64.f);
            float vlo = (ssq[rl * 4 + hb] + ssq[rl * 4 + hb + 1]) * (1.f / 64.f) - mlo * mlo;
            float rlo = rsqrtf(vlo + LN_EPS);
            float mhi = (ssum[(rl + 8) * 4 + hb] + ssum[(rl + 8) * 4 + hb + 1]) * (1.f / 64.f);
            float vhi = (ssq[(rl + 8) * 4 + hb] + ssq[(rl + 8) * 4 + hb + 1]) * (1.f / 64.f) - mhi * mhi;
            float rhi = rsqrtf(vhi + LN_EPS);
            int r0 = bm + rl;
            #pragma unroll
            for (int nt = 0; nt < 4; nt++) {
                int c = bn + wn + nt * 8 + tig * 2;
                int d = c & 63;
                float g0 = gv[d], g1 = gv[d + 1];
                float e0 = bv[d], e1 = bv[d + 1];
                float o0 = ((acc[mt][nt][0] - mlo) * rlo * g0 + e0) * qsc;
                float o1 = ((acc[mt][nt][1] - mlo) * rlo * g1 + e1) * qsc;
                float o2 = ((acc[mt][nt][2] - mhi) * rhi * g0 + e0) * qsc;
                float o3 = ((acc[mt][nt][3] - mhi) * rhi * g1 + e1) * qsc;
                *reinterpret_cast<uint32_t*>(Ch + (size_t)r0 * ldch + c) = h2pack(o0, o1);
                *reinterpret_cast<uint32_t*>(Ch + (size_t)(r0 + 8) * ldch + c) = h2pack(o2, o3);
            }
        }
        return;
    }

    #pragma unroll
    for (int mt = 0; mt < 4; mt++) {
        int r0 = bm + wm + mt * 16 + quad;
        #pragma unroll
        for (int nt = 0; nt < 4; nt++) {
            int c = bn + wn + nt * 8 + tig * 2;
            float2 v0 = make_float2(acc[mt][nt][0], acc[mt][nt][1]);
            float2 v1 = make_float2(acc[mt][nt][2], acc[mt][nt][3]);
            if (bias) {
                float bx = (c     < nbias) ? bias[c]     : 0.f;
                float by = (c + 1 < nbias) ? bias[c + 1] : 0.f;
                v0.x += bx; v0.y += by;
                v1.x += bx; v1.y += by;
            }
            if (mode == 2) {
                float2 ra = *reinterpret_cast<const float2*>(resid + (size_t)r0 * ldr + c);
                float2 rb = *reinterpret_cast<const float2*>(resid + (size_t)(r0 + 8) * ldr + c);
                v0.x += ra.x; v0.y += ra.y;
                v1.x += rb.x; v1.y += rb.y;
                *reinterpret_cast<float2*>(Cf + (size_t)r0 * ldcf + c) = v0;
                *reinterpret_cast<float2*>(Cf + (size_t)(r0 + 8) * ldcf + c) = v1;
            } else if (region == 1) {
                int d = c - 2 * DIMC;
                int hh = d >> 6, dd = d & 63;
                int bbk = r0 >> 11, nn = r0 & 2047;
                size_t base = ((size_t)(bbk * NHEADS + hh) * DHEAD);
                g_vt[(base + dd    ) * NSEQ + nn    ] = __float2half(v0.x);
                g_vt[(base + dd + 1) * NSEQ + nn    ] = __float2half(v0.y);
                g_vt[(base + dd    ) * NSEQ + nn + 8] = __float2half(v1.x);
                g_vt[(base + dd + 1) * NSEQ + nn + 8] = __float2half(v1.y);
            } else {
                if (mode == 3) {
                    v0.x = gelu1(v0.x); v0.y = gelu1(v0.y);
                    v1.x = gelu1(v1.x); v1.y = gelu1(v1.y);
                }
                *reinterpret_cast<uint32_t*>(Ch + (size_t)r0 * ldch + c) = h2pack(v0.x, v0.y);
                *reinterpret_cast<uint32_t*>(Ch + (size_t)(r0 + 8) * ldch + c) = h2pack(v1.x, v1.y);
            }
        }
    }
}

// ============================================================
// Flash attention: fp16 m16n8k16. No online max (LN-bounded scores),
// p = 2^s via ex2.approx.f16x2, l via ones-MMA. Triple-buffered K/V.
// P accumulator->A-operand layout coincidence: S accumulator half2
// packs (hl0/hl1) ARE the PV A-fragments — no SMEM round-trip.
// ============================================================
#define KSTRW 36
#define QWORDS (128 * KSTRW)
#define KVWORDS (64 * KSTRW)
#define ATTN_SMEM ((QWORDS + 6 * KVWORDS) * 4)   // 73728 B
#define ONESF  0x3C003C00u
#define CLAMP2 0x4BC04BC0u   // half2(15.5); score bound is ~13.3

__global__ void __launch_bounds__(256, 2)
fattn_kernel(const __half* __restrict__ fused, __half* __restrict__ aout, int bbase)
{
    extern __shared__ uint32_t smw[];
    uint32_t sbase = smem_u32(smw);

    int tid  = threadIdx.x;
    int wid  = tid >> 5, lane = tid & 31;
    int quad = lane >> 2, tig = lane & 3;
    int lane15 = lane & 15;
    int h  = blockIdx.y;
    int bb = blockIdx.z + bbase;
    int q0 = blockIdx.x * 128;
    int tq0 = bb * NSEQ + q0;
    int kvb = bb * NSEQ;
    const __half* vtb = g_vt + (size_t)(bb * NHEADS + h) * DHEAD * NSEQ;

    auto prefetch_kv = [&](int kt, int buf) {
        uint32_t dK = sbase + (uint32_t)(QWORDS + buf * 2 * KVWORDS) * 4;
        uint32_t dV = dK + KVWORDS * 4;
        #pragma unroll
        for (int i = 0; i < 2; i++) {
            int idx = i * 256 + tid;
            int r = idx >> 3, chh = (idx & 7) * 8;
            CP_CG(dK + (uint32_t)(r * KSTRW + chh / 2) * 4,
                  fused + (size_t)(kvb + kt + r) * FWP + DIMC + h * DHEAD + chh);
            CP_CG(dV + (uint32_t)(r * KSTRW + chh / 2) * 4,
                  vtb + (size_t)r * NSEQ + kt + chh);
        }
        CP_COMMIT();
    };

    #pragma unroll
    for (int i = 0; i < 4; i++) {
        int idx = i * 256 + tid;
        int r = idx >> 3, chh = (idx & 7) * 8;
        CP_CA(sbase + (uint32_t)(r * KSTRW + chh / 2) * 4,
              fused + (size_t)(tq0 + r) * FWP + h * DHEAD + chh);
    }
    prefetch_kv(0, 0);
    CP_WAIT(0);
    __syncthreads();

    uint32_t aPat = (uint32_t)(lane15 * KSTRW) * 4 + (lane >> 4) * 16;
    uint32_t bPat = (uint32_t)((((lane >> 4) << 3) + (lane & 7)) * KSTRW) * 4
                  + ((lane >> 3) & 1) * 16;

    uint32_t qf[4][4];
    {
        uint32_t qbase = sbase + (uint32_t)(wid * 16 * KSTRW) * 4 + aPat;
        #pragma unroll
        for (int kc = 0; kc < 4; kc++)
            ldsm4(qf[kc][0], qf[kc][1], qf[kc][2], qf[kc][3], qbase + kc * 32);
    }

    float o[8][4];
    #pragma unroll
    for (int i = 0; i < 8; i++)
        #pragma unroll
        for (int j = 0; j < 4; j++) o[i][j] = 0.f;
    float ls[4] = {0.f, 0.f, 0.f, 0.f};

    const int NT = NSEQ / 64;   // 32 tiles
    for (int t = 0; t < NT; t++) {
        int b = t % 3;
        if (t + 1 < NT) prefetch_kv((t + 1) * 64, (t + 1) % 3);

        uint32_t kBase = sbase + (uint32_t)(QWORDS + b * 2 * KVWORDS) * 4;
        uint32_t vBase = kBase + KVWORDS * 4;

        float sc[8][4];
        #pragma unroll
        for (int i = 0; i < 8; i++)
            #pragma unroll
            for (int j = 0; j < 4; j++) sc[i][j] = 0.f;

        #pragma unroll
        for (int kc = 0; kc < 4; kc++) {
            #pragma unroll
            for (int np = 0; np < 4; np++) {
                uint32_t b00, b01, b10, b11;
                ldsm4(b00, b01, b10, b11,
                      kBase + (uint32_t)(np * 16 * KSTRW) * 4 + bPat + kc * 32);
                mma_f16(sc[2*np][0], sc[2*np][1], sc[2*np][2], sc[2*np][3],
                        qf[kc][0], qf[kc][1], qf[kc][2], qf[kc][3], b00, b01);
                mma_f16(sc[2*np+1][0], sc[2*np+1][1], sc[2*np+1][2], sc[2*np+1][3],
                        qf[kc][0], qf[kc][1], qf[kc][2], qf[kc][3], b10, b11);
            }
        }

        // p = 2^s; half2 packs of the S accumulator ARE the PV A-fragments
        uint32_t hl0[8], hl1[8];
        #pragma unroll
        for (int nf = 0; nf < 8; nf++) {
            hl0[nf] = h2exp2(h2minc(h2pack(sc[nf][0], sc[nf][1]), CLAMP2));
            hl1[nf] = h2exp2(h2minc(h2pack(sc[nf][2], sc[nf][3]), CLAMP2));
        }

        #pragma unroll
        for (int kc = 0; kc < 4; kc++) {
            uint32_t a0 = hl0[2*kc], a1 = hl1[2*kc];
            uint32_t a2 = hl0[2*kc+1], a3 = hl1[2*kc+1];
            mma_f16(ls[0], ls[1], ls[2], ls[3], a0, a1, a2, a3, ONESF, ONESF);
            #pragma unroll
            for (int np = 0; np < 4; np++) {
                uint32_t b00, b01, b10, b11;
                ldsm4(b00, b01, b10, b11,
                      vBase + (uint32_t)(np * 16 * KSTRW) * 4 + bPat + kc * 32);
                mma_f16(o[2*np][0], o[2*np][1], o[2*np][2], o[2*np][3],
                        a0, a1, a2, a3, b00, b01);
                mma_f16(o[2*np+1][0], o[2*np+1][1], o[2*np+1][2], o[2*np+1][3],
                        a0, a1, a2, a3, b10, b11);
            }
        }

        if (t + 1 < NT) { CP_WAIT(0); }
        if ((t & 1) && (t + 1 < NT)) __syncthreads();   // barrier every other tile
    }

    float il0 = 1.f / ls[0], il1 = 1.f / ls[2];
    int r0 = tq0 + wid * 16 + quad;
    #pragma unroll
    for (int nf = 0; nf < 8; nf++) {
        int c = h * DHEAD + nf * 8 + tig * 2;
        *reinterpret_cast<uint32_t*>(aout + (size_t)r0 * DIMC + c) =
            h2pack(o[nf][0] * il0, o[nf][1] * il0);
        *reinterpret_cast<uint32_t*>(aout + (size_t)(r0 + 8) * DIMC + c) =
            h2pack(o[nf][2] * il1, o[nf][3] * il1);
    }
}

// ============================================================
// launch — exact R12/R15 schedule (verified best)
// ============================================================
extern "C" void kernel_launch(void* const* d_in, const int* in_sizes, int n_in,
                              void* d_out, int out_size)
{
    const float* x      = (const float*)d_in[0];
    const float* norm_g = (const float*)d_in[1];
    const float* norm_b = (const float*)d_in[2];
    const float* W1     = (const float*)d_in[3];
    const float* b1     = (const float*)d_in[4];
    const float* qn_g   = (const float*)d_in[5];
    const float* qn_b   = (const float*)d_in[6];
    const float* kn_g   = (const float*)d_in[7];
    const float* kn_b   = (const float*)d_in[8];
    const float* Wao    = (const float*)d_in[9];
    const float* bao    = (const float*)d_in[10];
    const float* Wmo    = (const float*)d_in[11];
    const float* bmo    = (const float*)d_in[12];
    const float* W2     = (const float*)d_in[13];
    const float* b2     = (const float*)d_in[14];
    float*       out    = (float*)d_out;

    __half *norm, *fused, *attn, *w1t, *wfa, *wfm;
    float *beff;
    cudaGetSymbolAddress((void**)&norm,  g_norm);
    cudaGetSymbolAddress((void**)&fused, g_fused);
    cudaGetSymbolAddress((void**)&attn,  g_attn);
    cudaGetSymbolAddress((void**)&w1t,   g_w1t);
    cudaGetSymbolAddress((void**)&wfa,   g_wfa);
    cudaGetSymbolAddress((void**)&wfm,   g_wfm);
    cudaGetSymbolAddress((void**)&beff,  g_beff);

    static bool inited = false;
    static cudaStream_t s2;
    static cudaEvent_t ev1, evw1, evg1, ev3;
    if (!inited) {
        cudaStreamCreateWithFlags(&s2, cudaStreamNonBlocking);
        cudaEventCreateWithFlags(&ev1, cudaEventDisableTiming);
        cudaEventCreateWithFlags(&evw1, cudaEventDisableTiming);
        cudaEventCreateWithFlags(&evg1, cudaEventDisableTiming);
        cudaEventCreateWithFlags(&ev3, cudaEventDisableTiming);
        cudaFuncSetAttribute(mma_gemm, cudaFuncAttributeMaxDynamicSharedMemorySize, GEMM_SMEM);
        cudaFuncSetAttribute(fold_kernel, cudaFuncAttributeMaxDynamicSharedMemorySize, GEMM_SMEM);
        cudaFuncSetAttribute(fattn_kernel, cudaFuncAttributeMaxDynamicSharedMemorySize, ATTN_SMEM);
        inited = true;
    }

    // ---- fork: side chain (prep_w1 -> prep_rest -> fold), later the mlp slice
    cudaEventRecord(ev1, 0);
    cudaStreamWaitEvent(s2, ev1, 0);
    prep_w1_kernel<<<3840, 256, 0, s2>>>(W1);
    cudaEventRecord(evw1, s2);
    prep_rest_kernel<<<9280, 256, 0, s2>>>(W2, Wao, Wmo, bao, bmo, b2);
    fold_kernel<<<116, 256, GEMM_SMEM, s2>>>();

    // ---- main chain: ln concurrent with prep_w1
    ln_kernel<<<NTOK, 256>>>(x, norm_g, norm_b, norm);
    cudaStreamWaitEvent(0, evw1, 0);

    // GEMM1-qkv (cols 0..3071): qk->LN'd fused, V->g_vt transposed
    mma_gemm<<<dim3(24, NTOK / 128), 256, GEMM_SMEM>>>(
        norm, DIMC, w1t, DIMC, DIMC,
        nullptr, 0, nullptr, 0, 0,
        fused, FWP, nullptr, 0, b1, FW, nullptr, 0,
        qn_g, qn_b, kn_g, kn_b, 0, 1);
    cudaEventRecord(evg1, 0);

    // side stream: GEMM1-mlp slice (cols 3072.., gelu) overlaps fattn
    cudaStreamWaitEvent(s2, evg1, 0);
    mma_gemm<<<dim3(6, NTOK / 128), 256, GEMM_SMEM, s2>>>(
        norm, DIMC, w1t + (size_t)(3 * DIMC) * DIMC, DIMC, DIMC,
        nullptr, 0, nullptr, 0, 0,
        fused + 3 * DIMC, FWP, nullptr, 0, b1 + 3 * DIMC, FW - 3 * DIMC, nullptr, 0,
        nullptr, nullptr, nullptr, nullptr, 0, 3);
    cudaEventRecord(ev3, s2);

    // flash attention (monolithic, main stream)
    fattn_kernel<<<dim3(NSEQ / 128, NHEADS, 2), 256, ATTN_SMEM>>>(fused, attn, 0);

    // ---- join, then apply: out = x + attn @ wfa^T + gelu_hidden @ wfm^T + beff
    cudaStreamWaitEvent(0, ev3, 0);
    mma_gemm<<<dim3(DIMC / 128, NTOK / 128), 256, GEMM_SMEM>>>(
        attn, DIMC, wfa, DIMC, DIMC,
        fused + 3 * DIMC, FWP, wfm, HIDPAD, HIDPAD,
        nullptr, 0, out, DIMC, beff, DIMC, x, DIMC,
        nullptr, nullptr, nullptr, nullptr, 0, 2);
}